// round 1
// baseline (speedup 1.0000x reference)
#include <cuda_runtime.h>
#include <math.h>

#define N_NODES   100000
#define N_EDGES   3200000
#define IN_CH     200
#define HID       64
#define N_GRAPHS  500
#define OUT_CH    2

#define SCAN_CHUNK 1024
#define NB ((N_NODES + SCAN_CHUNK - 1) / SCAN_CHUNK)   // 98

// ---------------- scratch (device globals; no allocation allowed) ----------
__device__ float g_deg[N_NODES];            // deg, then dinv (in place)
__device__ int   g_cnt[N_NODES];
__device__ int   g_fill[N_NODES];
__device__ int   g_starts[N_NODES + 1];
__device__ int   g_bsum[128];
__device__ int   g_srcs[N_EDGES];
__device__ float g_nrm[N_EDGES];
__device__ float g_bufA[(size_t)N_NODES * HID];
__device__ float g_bufB[(size_t)N_NODES * HID];
__device__ float g_pooled[N_GRAPHS * HID];
__device__ int   g_cntg[N_GRAPHS];

// ---------------- init ----------------
__global__ void k_zero() {
    int i = blockIdx.x * blockDim.x + threadIdx.x;
    if (i < N_NODES) { g_deg[i] = 0.f; g_cnt[i] = 0; g_fill[i] = 0; }
    if (i < N_GRAPHS * HID) g_pooled[i] = 0.f;
    if (i < N_GRAPHS) g_cntg[i] = 0;
}

// ---------------- degree histogram ----------------
__global__ void k_hist(const int* __restrict__ col, const float* __restrict__ wa) {
    int e = blockIdx.x * blockDim.x + threadIdx.x;
    if (e >= N_EDGES) return;
    int c = col[e];
    atomicAdd(&g_cnt[c], 1);
    atomicAdd(&g_deg[c], fabsf(wa[e]));
}

__global__ void k_dinv() {
    int i = blockIdx.x * blockDim.x + threadIdx.x;
    if (i < N_NODES) g_deg[i] = rsqrtf(g_deg[i] + 1.0f);
}

// ---------------- exclusive scan of g_cnt -> g_starts ----------------
__global__ void k_scan1() {   // grid NB, block 1024: per-block sums
    __shared__ int sh[SCAN_CHUNK];
    int idx = blockIdx.x * SCAN_CHUNK + threadIdx.x;
    sh[threadIdx.x] = (idx < N_NODES) ? g_cnt[idx] : 0;
    __syncthreads();
    for (int off = SCAN_CHUNK / 2; off > 0; off >>= 1) {
        if (threadIdx.x < off) sh[threadIdx.x] += sh[threadIdx.x + off];
        __syncthreads();
    }
    if (threadIdx.x == 0) g_bsum[blockIdx.x] = sh[0];
}

__global__ void k_scan2() {   // 1 block: exclusive scan of block sums
    __shared__ int sh[128];
    int t = threadIdx.x;
    sh[t] = (t < NB) ? g_bsum[t] : 0;
    __syncthreads();
    if (t == 0) {
        int acc = 0;
        for (int b = 0; b < NB; b++) { int v = sh[b]; g_bsum[b] = acc; acc += v; }
        g_starts[N_NODES] = N_EDGES;
    }
}

__global__ void k_scan3() {   // grid NB, block 1024: Hillis-Steele + offset
    __shared__ int sh[SCAN_CHUNK];
    int idx = blockIdx.x * SCAN_CHUNK + threadIdx.x;
    int v = (idx < N_NODES) ? g_cnt[idx] : 0;
    sh[threadIdx.x] = v;
    __syncthreads();
    for (int off = 1; off < SCAN_CHUNK; off <<= 1) {
        int t = (threadIdx.x >= off) ? sh[threadIdx.x - off] : 0;
        __syncthreads();
        sh[threadIdx.x] += t;
        __syncthreads();
    }
    if (idx < N_NODES) g_starts[idx] = g_bsum[blockIdx.x] + sh[threadIdx.x] - v;
}

// ---------------- CSR fill (by destination) ----------------
__global__ void k_fill(const int* __restrict__ row, const int* __restrict__ col,
                       const float* __restrict__ wa) {
    int e = blockIdx.x * blockDim.x + threadIdx.x;
    if (e >= N_EDGES) return;
    int c = col[e];
    int r = row[e];
    int p = g_starts[c] + atomicAdd(&g_fill[c], 1);
    g_srcs[p] = r;
    g_nrm[p]  = g_deg[r] * fabsf(wa[e]) * g_deg[c];   // g_deg holds dinv now
}

// ---------------- fp32 SIMT GEMM: C[M,64] = A[M,K] @ W[K,64] ----------------
template <int K>
__device__ __forceinline__ void gemm_impl(const float* __restrict__ A,
                                          const float* __restrict__ W,
                                          float* __restrict__ C) {
    __shared__ __align__(16) float xs[8][128];
    __shared__ __align__(16) float ws[8][64];
    const int M = N_NODES;
    int tid = threadIdx.x;
    int m0  = blockIdx.x * 128;
    int r0  = (tid >> 4) * 8;
    int c0  = (tid & 15) * 4;

    float4 acc[8];
#pragma unroll
    for (int i = 0; i < 8; i++) acc[i] = make_float4(0.f, 0.f, 0.f, 0.f);

    int ml = tid & 127;
    int kq = (tid >> 7) * 4;          // 0 or 4
    int mg = m0 + ml;
    const float* Arow = A + (size_t)mg * K;

    for (int k0 = 0; k0 < K; k0 += 8) {
        float4 xv = make_float4(0.f, 0.f, 0.f, 0.f);
        if (mg < M) xv = *(const float4*)(Arow + k0 + kq);
        if (tid < 128) {
            int kk = tid >> 4;
            int c  = (tid & 15) * 4;
            *(float4*)&ws[kk][c] = *(const float4*)(W + (k0 + kk) * 64 + c);
        }
        xs[kq + 0][ml] = xv.x;
        xs[kq + 1][ml] = xv.y;
        xs[kq + 2][ml] = xv.z;
        xs[kq + 3][ml] = xv.w;
        __syncthreads();
#pragma unroll
        for (int kk = 0; kk < 8; kk++) {
            float4 w4 = *(float4*)&ws[kk][c0];
            float4 a0 = *(float4*)&xs[kk][r0];
            float4 a1 = *(float4*)&xs[kk][r0 + 4];
            float a[8] = {a0.x, a0.y, a0.z, a0.w, a1.x, a1.y, a1.z, a1.w};
#pragma unroll
            for (int i = 0; i < 8; i++) {
                acc[i].x = fmaf(a[i], w4.x, acc[i].x);
                acc[i].y = fmaf(a[i], w4.y, acc[i].y);
                acc[i].z = fmaf(a[i], w4.z, acc[i].z);
                acc[i].w = fmaf(a[i], w4.w, acc[i].w);
            }
        }
        __syncthreads();
    }
#pragma unroll
    for (int i = 0; i < 8; i++) {
        int m = m0 + r0 + i;
        if (m < M) *(float4*)(C + (size_t)m * 64 + c0) = acc[i];
    }
}

__global__ void __launch_bounds__(256) k_gemm1(const float* __restrict__ x,
                                               const float* __restrict__ W1) {
    gemm_impl<IN_CH>(x, W1, g_bufA);
}
__global__ void __launch_bounds__(256) k_gemm2(const float* __restrict__ W2) {
    gemm_impl<HID>(g_bufB, W2, g_bufA);
}

// ---------------- warp-per-node CSR gather + self-loop + bias + relu -------
// in: g_bufA (pre-activation h), out: g_bufB
__global__ void __launch_bounds__(256) k_gather(const float* __restrict__ bias,
                                                const int* __restrict__ batch,
                                                int dopool) {
    int wid  = (blockIdx.x * blockDim.x + threadIdx.x) >> 5;
    int lane = threadIdx.x & 31;
    if (wid >= N_NODES) return;
    const float* __restrict__ h = g_bufA;
    int n = wid;
    int s = g_starts[n];
    int e = g_starts[n + 1];
    int f = lane * 2;
    float ax = 0.f, ay = 0.f;
    for (int i = s; i < e; i += 32) {
        int rem = e - i;
        int src = 0; float nv = 0.f;
        if (lane < rem) { src = g_srcs[i + lane]; nv = g_nrm[i + lane]; }
        int m = rem < 32 ? rem : 32;
#pragma unroll 4
        for (int j = 0; j < m; j++) {
            int   sj = __shfl_sync(0xffffffffu, src, j);
            float nj = __shfl_sync(0xffffffffu, nv, j);
            float2 hv = *(const float2*)(h + (size_t)sj * 64 + f);
            ax = fmaf(nj, hv.x, ax);
            ay = fmaf(nj, hv.y, ay);
        }
    }
    // self-loop: dinv^2 * h[n], then bias, relu
    float d  = g_deg[n];
    float d2 = d * d;
    float2 hn = *(const float2*)(h + (size_t)n * 64 + f);
    ax = fmaf(d2, hn.x, ax) + bias[f];
    ay = fmaf(d2, hn.y, ay) + bias[f + 1];
    ax = fmaxf(ax, 0.f);
    ay = fmaxf(ay, 0.f);
    *(float2*)(g_bufB + (size_t)n * 64 + f) = make_float2(ax, ay);
    if (dopool) {
        int g = batch[n];
        atomicAdd(&g_pooled[g * 64 + f],     ax);
        atomicAdd(&g_pooled[g * 64 + f + 1], ay);
        if (lane == 0) atomicAdd(&g_cntg[g], 1);
    }
}

// ---------------- final MLP: mean-pool -> L1+relu -> L2 -> out -------------
__global__ void __launch_bounds__(256) k_mlp(const float* __restrict__ L1,
                                             const float* __restrict__ c1,
                                             const float* __restrict__ L2,
                                             const float* __restrict__ c2,
                                             float* __restrict__ out) {
    int g = blockIdx.x;
    __shared__ float pm[HID];
    __shared__ float fea[IN_CH];
    __shared__ float red[256];
    int tid = threadIdx.x;
    if (tid < HID) {
        float cv = (float)g_cntg[g];
        pm[tid] = g_pooled[g * HID + tid] / fmaxf(cv, 1.0f);
    }
    __syncthreads();
    if (tid < IN_CH) {
        float s = c1[tid];
#pragma unroll
        for (int k = 0; k < HID; k++) s = fmaf(pm[k], L1[k * IN_CH + tid], s);
        fea[tid] = fmaxf(s, 0.f);
    }
    __syncthreads();
    float p0 = 0.f, p1 = 0.f;
    if (tid < IN_CH) {
        float fv = fea[tid];
        p0 = fv * L2[tid * OUT_CH];
        p1 = fv * L2[tid * OUT_CH + 1];
    }
    red[tid] = p0; __syncthreads();
    for (int off = 128; off > 0; off >>= 1) {
        if (tid < off) red[tid] += red[tid + off];
        __syncthreads();
    }
    float s0 = red[0];
    __syncthreads();
    red[tid] = p1; __syncthreads();
    for (int off = 128; off > 0; off >>= 1) {
        if (tid < off) red[tid] += red[tid + off];
        __syncthreads();
    }
    if (tid == 0) {
        out[g * OUT_CH]     = s0     + c2[0];
        out[g * OUT_CH + 1] = red[0] + c2[1];
    }
}

// ---------------- launch ----------------
extern "C" void kernel_launch(void* const* d_in, const int* in_sizes, int n_in,
                              void* d_out, int out_size) {
    const float* x         = (const float*)d_in[0];
    const int*   edge_idx  = (const int*)d_in[1];
    const float* edge_attr = (const float*)d_in[2];
    const int*   batch     = (const int*)d_in[3];
    const float* W1        = (const float*)d_in[4];
    const float* b1        = (const float*)d_in[5];
    const float* W2        = (const float*)d_in[6];
    const float* b2        = (const float*)d_in[7];
    const float* L1        = (const float*)d_in[8];
    const float* c1        = (const float*)d_in[9];
    const float* L2        = (const float*)d_in[10];
    const float* c2        = (const float*)d_in[11];
    float* out = (float*)d_out;

    const int* row = edge_idx;
    const int* col = edge_idx + N_EDGES;

    const int TB = 256;
    int nodeBlocks = (N_NODES + TB - 1) / TB;
    int edgeBlocks = (N_EDGES + TB - 1) / TB;
    int gemmBlocks = (N_NODES + 127) / 128;
    int gatherBlocks = (N_NODES * 32 + TB - 1) / TB;

    k_zero<<<nodeBlocks, TB>>>();
    k_hist<<<edgeBlocks, TB>>>(col, edge_attr);
    k_dinv<<<nodeBlocks, TB>>>();
    k_scan1<<<NB, SCAN_CHUNK>>>();
    k_scan2<<<1, 128>>>();
    k_scan3<<<NB, SCAN_CHUNK>>>();
    k_fill<<<edgeBlocks, TB>>>(row, col, edge_attr);

    k_gemm1<<<gemmBlocks, 256>>>(x, W1);            // g_bufA = x @ W1
    k_gather<<<gatherBlocks, TB>>>(b1, batch, 0);   // g_bufB = relu(agg + selfloop + b1)
    k_gemm2<<<gemmBlocks, 256>>>(W2);               // g_bufA = g_bufB @ W2
    k_gather<<<gatherBlocks, TB>>>(b2, batch, 1);   // g_bufB + pooling atomics
    k_mlp<<<N_GRAPHS, 256>>>(L1, c1, L2, c2, out);
}

// round 2
// speedup vs baseline: 1.1713x; 1.1713x over previous
#include <cuda_runtime.h>
#include <math.h>

#define N_NODES   100000
#define N_EDGES   3200000
#define IN_CH     200
#define HID       64
#define N_GRAPHS  500
#define OUT_CH    2

#define SCAN_CHUNK 1024
#define NB ((N_NODES + SCAN_CHUNK - 1) / SCAN_CHUNK)   // 98

// ---------------- scratch (device globals; no allocation allowed) ----------
__device__ float g_deg[N_NODES];            // deg sum, then dinv (in place)
__device__ int   g_cnt[N_NODES];
__device__ int   g_cursor[N_NODES];         // fill cursor, pre-seeded = starts
__device__ int   g_starts[N_NODES + 1];
__device__ int   g_bsum[128];
__device__ int2  g_edges[N_EDGES];          // {src, __float_as_int(|w|)}
__device__ float g_bufA[(size_t)N_NODES * HID];
__device__ float g_bufB[(size_t)N_NODES * HID];
__device__ float g_pooled[N_GRAPHS * HID];
__device__ int   g_cntg[N_GRAPHS];

// ---------------- init ----------------
__global__ void k_zero() {
    int i = blockIdx.x * blockDim.x + threadIdx.x;
    if (i < N_NODES) { g_deg[i] = 0.f; g_cnt[i] = 0; }
    if (i < N_GRAPHS * HID) g_pooled[i] = 0.f;
    if (i < N_GRAPHS) g_cntg[i] = 0;
}

// ---------------- degree histogram (4 edges / thread, vectorized loads) ----
__global__ void k_hist(const int4* __restrict__ col4, const float4* __restrict__ wa4) {
    int i = blockIdx.x * blockDim.x + threadIdx.x;
    if (i >= N_EDGES / 4) return;
    int4   c = col4[i];
    float4 w = wa4[i];
    atomicAdd(&g_cnt[c.x], 1); atomicAdd(&g_deg[c.x], fabsf(w.x));
    atomicAdd(&g_cnt[c.y], 1); atomicAdd(&g_deg[c.y], fabsf(w.y));
    atomicAdd(&g_cnt[c.z], 1); atomicAdd(&g_deg[c.z], fabsf(w.z));
    atomicAdd(&g_cnt[c.w], 1); atomicAdd(&g_deg[c.w], fabsf(w.w));
}

__global__ void k_dinv() {
    int i = blockIdx.x * blockDim.x + threadIdx.x;
    if (i < N_NODES) g_deg[i] = rsqrtf(g_deg[i] + 1.0f);
}

// ---------------- exclusive scan of g_cnt -> g_starts (+ seed g_cursor) ----
__global__ void k_scan1() {
    __shared__ int sh[SCAN_CHUNK];
    int idx = blockIdx.x * SCAN_CHUNK + threadIdx.x;
    sh[threadIdx.x] = (idx < N_NODES) ? g_cnt[idx] : 0;
    __syncthreads();
    for (int off = SCAN_CHUNK / 2; off > 0; off >>= 1) {
        if (threadIdx.x < off) sh[threadIdx.x] += sh[threadIdx.x + off];
        __syncthreads();
    }
    if (threadIdx.x == 0) g_bsum[blockIdx.x] = sh[0];
}

__global__ void k_scan2() {
    __shared__ int sh[128];
    int t = threadIdx.x;
    sh[t] = (t < NB) ? g_bsum[t] : 0;
    __syncthreads();
    if (t == 0) {
        int acc = 0;
        for (int b = 0; b < NB; b++) { int v = sh[b]; g_bsum[b] = acc; acc += v; }
        g_starts[N_NODES] = N_EDGES;
    }
}

__global__ void k_scan3() {
    __shared__ int sh[SCAN_CHUNK];
    int idx = blockIdx.x * SCAN_CHUNK + threadIdx.x;
    int v = (idx < N_NODES) ? g_cnt[idx] : 0;
    sh[threadIdx.x] = v;
    __syncthreads();
    for (int off = 1; off < SCAN_CHUNK; off <<= 1) {
        int t = (threadIdx.x >= off) ? sh[threadIdx.x - off] : 0;
        __syncthreads();
        sh[threadIdx.x] += t;
        __syncthreads();
    }
    if (idx < N_NODES) {
        int st = g_bsum[blockIdx.x] + sh[threadIdx.x] - v;
        g_starts[idx] = st;
        g_cursor[idx] = st;       // pre-seed fill cursor
    }
}

// ---------------- CSR fill (no dinv reads; single 8B packed store) ---------
__global__ void k_fill(const int* __restrict__ row, const int* __restrict__ col,
                       const float* __restrict__ wa) {
    int e = blockIdx.x * blockDim.x + threadIdx.x;
    if (e >= N_EDGES) return;
    int c = col[e];
    int p = atomicAdd(&g_cursor[c], 1);
    g_edges[p] = make_int2(row[e], __float_as_int(fabsf(wa[e])));
}

// ---------------- fp32 SIMT GEMM: C[m,:] = dinv[m] * (A[m,:] @ W) ----------
template <int K>
__device__ __forceinline__ void gemm_impl(const float* __restrict__ A,
                                          const float* __restrict__ W,
                                          float* __restrict__ C) {
    __shared__ __align__(16) float xs[8][128];
    __shared__ __align__(16) float ws[8][64];
    const int M = N_NODES;
    int tid = threadIdx.x;
    int m0  = blockIdx.x * 128;
    int r0  = (tid >> 4) * 8;
    int c0  = (tid & 15) * 4;

    float4 acc[8];
#pragma unroll
    for (int i = 0; i < 8; i++) acc[i] = make_float4(0.f, 0.f, 0.f, 0.f);

    int ml = tid & 127;
    int kq = (tid >> 7) * 4;          // 0 or 4
    int mg = m0 + ml;
    const float* Arow = A + (size_t)mg * K;

    for (int k0 = 0; k0 < K; k0 += 8) {
        float4 xv = make_float4(0.f, 0.f, 0.f, 0.f);
        if (mg < M) xv = *(const float4*)(Arow + k0 + kq);
        if (tid < 128) {
            int kk = tid >> 4;
            int c  = (tid & 15) * 4;
            *(float4*)&ws[kk][c] = *(const float4*)(W + (k0 + kk) * 64 + c);
        }
        xs[kq + 0][ml] = xv.x;
        xs[kq + 1][ml] = xv.y;
        xs[kq + 2][ml] = xv.z;
        xs[kq + 3][ml] = xv.w;
        __syncthreads();
#pragma unroll
        for (int kk = 0; kk < 8; kk++) {
            float4 w4 = *(float4*)&ws[kk][c0];
            float4 a0 = *(float4*)&xs[kk][r0];
            float4 a1 = *(float4*)&xs[kk][r0 + 4];
            float a[8] = {a0.x, a0.y, a0.z, a0.w, a1.x, a1.y, a1.z, a1.w};
#pragma unroll
            for (int i = 0; i < 8; i++) {
                acc[i].x = fmaf(a[i], w4.x, acc[i].x);
                acc[i].y = fmaf(a[i], w4.y, acc[i].y);
                acc[i].z = fmaf(a[i], w4.z, acc[i].z);
                acc[i].w = fmaf(a[i], w4.w, acc[i].w);
            }
        }
        __syncthreads();
    }
#pragma unroll
    for (int i = 0; i < 8; i++) {
        int m = m0 + r0 + i;
        if (m < M) {
            float d = g_deg[m];                 // dinv (row scale)
            float4 v = acc[i];
            v.x *= d; v.y *= d; v.z *= d; v.w *= d;
            *(float4*)(C + (size_t)m * 64 + c0) = v;
        }
    }
}

__global__ void __launch_bounds__(256) k_gemm1(const float* __restrict__ x,
                                               const float* __restrict__ W1) {
    gemm_impl<IN_CH>(x, W1, g_bufA);
}
__global__ void __launch_bounds__(256) k_gemm2(const float* __restrict__ W2) {
    gemm_impl<HID>(g_bufB, W2, g_bufA);
}

// --- warp-per-node gather: out = relu(dinv[n]*(sum w*h'[src] + h'[n]) + b) -
__global__ void __launch_bounds__(256) k_gather(const float* __restrict__ bias,
                                                const int* __restrict__ batch,
                                                int dopool) {
    int wid  = (blockIdx.x * blockDim.x + threadIdx.x) >> 5;
    int lane = threadIdx.x & 31;
    if (wid >= N_NODES) return;
    const float* __restrict__ h = g_bufA;
    int s = g_starts[wid];
    int e = g_starts[wid + 1];
    int f = lane * 2;
    float ax = 0.f, ay = 0.f;
    for (int i = s; i < e; i += 32) {
        int rem = e - i;
        int2 ed = make_int2(0, 0);
        if (lane < rem) ed = g_edges[i + lane];
        int m = rem < 32 ? rem : 32;
#pragma unroll 4
        for (int j = 0; j < m; j++) {
            int   sj = __shfl_sync(0xffffffffu, ed.x, j);
            float wj = __int_as_float(__shfl_sync(0xffffffffu, ed.y, j));
            float2 hv = *(const float2*)(h + (size_t)sj * 64 + f);
            ax = fmaf(wj, hv.x, ax);
            ay = fmaf(wj, hv.y, ay);
        }
    }
    float2 hn = *(const float2*)(h + (size_t)wid * 64 + f);
    float d = g_deg[wid];
    ax = fmaf(d, ax + hn.x, bias[f]);
    ay = fmaf(d, ay + hn.y, bias[f + 1]);
    ax = fmaxf(ax, 0.f);
    ay = fmaxf(ay, 0.f);
    if (!dopool) {
        *(float2*)(g_bufB + (size_t)wid * 64 + f) = make_float2(ax, ay);
    } else {
        int g = batch[wid];
        atomicAdd(&g_pooled[g * 64 + f],     ax);
        atomicAdd(&g_pooled[g * 64 + f + 1], ay);
        if (lane == 0) atomicAdd(&g_cntg[g], 1);
    }
}

// ---------------- final MLP ----------------
__global__ void __launch_bounds__(256) k_mlp(const float* __restrict__ L1,
                                             const float* __restrict__ c1,
                                             const float* __restrict__ L2,
                                             const float* __restrict__ c2,
                                             float* __restrict__ out) {
    int g = blockIdx.x;
    __shared__ float pm[HID];
    __shared__ float fea[IN_CH];
    __shared__ float red[256];
    int tid = threadIdx.x;
    if (tid < HID) {
        float cv = (float)g_cntg[g];
        pm[tid] = g_pooled[g * HID + tid] / fmaxf(cv, 1.0f);
    }
    __syncthreads();
    if (tid < IN_CH) {
        float s = c1[tid];
#pragma unroll
        for (int k = 0; k < HID; k++) s = fmaf(pm[k], L1[k * IN_CH + tid], s);
        fea[tid] = fmaxf(s, 0.f);
    }
    __syncthreads();
    float p0 = 0.f, p1 = 0.f;
    if (tid < IN_CH) {
        float fv = fea[tid];
        p0 = fv * L2[tid * OUT_CH];
        p1 = fv * L2[tid * OUT_CH + 1];
    }
    red[tid] = p0; __syncthreads();
    for (int off = 128; off > 0; off >>= 1) {
        if (tid < off) red[tid] += red[tid + off];
        __syncthreads();
    }
    float s0 = red[0];
    __syncthreads();
    red[tid] = p1; __syncthreads();
    for (int off = 128; off > 0; off >>= 1) {
        if (tid < off) red[tid] += red[tid + off];
        __syncthreads();
    }
    if (tid == 0) {
        out[g * OUT_CH]     = s0     + c2[0];
        out[g * OUT_CH + 1] = red[0] + c2[1];
    }
}

// ---------------- launch ----------------
extern "C" void kernel_launch(void* const* d_in, const int* in_sizes, int n_in,
                              void* d_out, int out_size) {
    const float* x         = (const float*)d_in[0];
    const int*   edge_idx  = (const int*)d_in[1];
    const float* edge_attr = (const float*)d_in[2];
    const int*   batch     = (const int*)d_in[3];
    const float* W1        = (const float*)d_in[4];
    const float* b1        = (const float*)d_in[5];
    const float* W2        = (const float*)d_in[6];
    const float* b2        = (const float*)d_in[7];
    const float* L1        = (const float*)d_in[8];
    const float* c1        = (const float*)d_in[9];
    const float* L2        = (const float*)d_in[10];
    const float* c2        = (const float*)d_in[11];
    float* out = (float*)d_out;

    const int* row = edge_idx;
    const int* col = edge_idx + N_EDGES;

    // One-time host resources (created on the correctness call, before graph
    // capture; no device memory is allocated).
    static cudaStream_t s2 = nullptr;
    static cudaEvent_t  evF = nullptr, evJ = nullptr;
    if (s2 == nullptr) {
        cudaStreamCreateWithFlags(&s2, cudaStreamNonBlocking);
        cudaEventCreateWithFlags(&evF, cudaEventDisableTiming);
        cudaEventCreateWithFlags(&evJ, cudaEventDisableTiming);
    }

    const int TB = 256;
    int nodeBlocks   = (N_NODES + TB - 1) / TB;
    int edgeBlocks   = (N_EDGES + TB - 1) / TB;
    int histBlocks   = (N_EDGES / 4 + TB - 1) / TB;
    int gemmBlocks   = (N_NODES + 127) / 128;
    int gatherBlocks = (N_NODES * 32 + TB - 1) / TB;

    k_zero<<<nodeBlocks, TB>>>();
    k_hist<<<histBlocks, TB>>>((const int4*)col, (const float4*)edge_attr);
    k_dinv<<<nodeBlocks, TB>>>();

    // fork: GEMM1 (needs only dinv) runs concurrently with scan+fill
    cudaEventRecord(evF, 0);
    cudaStreamWaitEvent(s2, evF, 0);
    k_gemm1<<<gemmBlocks, 256, 0, s2>>>(x, W1);     // g_bufA = dinv * (x @ W1)
    cudaEventRecord(evJ, s2);

    k_scan1<<<NB, SCAN_CHUNK>>>();
    k_scan2<<<1, 128>>>();
    k_scan3<<<NB, SCAN_CHUNK>>>();
    k_fill<<<edgeBlocks, TB>>>(row, col, edge_attr);

    cudaStreamWaitEvent(0, evJ, 0);                  // join before gather1

    k_gather<<<gatherBlocks, TB>>>(b1, batch, 0);    // g_bufB = layer1 out
    k_gemm2<<<gemmBlocks, 256>>>(W2);                // g_bufA = dinv * (bufB @ W2)
    k_gather<<<gatherBlocks, TB>>>(b2, batch, 1);    // pooling only
    k_mlp<<<N_GRAPHS, 256>>>(L1, c1, L2, c2, out);
}

// round 3
// speedup vs baseline: 1.1860x; 1.0125x over previous
#include <cuda_runtime.h>
#include <cuda_bf16.h>
#include <math.h>

#define N_NODES   100000
#define N_EDGES   3200000
#define IN_CH     200
#define HID       64
#define N_GRAPHS  500
#define OUT_CH    2

#define SCAN_CHUNK 1024
#define NB ((N_NODES + SCAN_CHUNK - 1) / SCAN_CHUNK)   // 98

// ---------------- scratch (device globals; no allocation allowed) ----------
__device__ float g_deg[N_NODES];            // deg sum, then dinv (in place)
__device__ int   g_cnt[N_NODES];
__device__ int   g_cursor[N_NODES];
__device__ int   g_starts[N_NODES + 1];
__device__ int   g_bsum[128];
__device__ int2  g_edges[N_EDGES];          // {src, |w| bits}
__device__ float g_bufA[(size_t)N_NODES * HID];            // raw x@W1 (fp32)
__device__ __nv_bfloat162 g_hbf[(size_t)N_NODES * (HID/2)];// h' = dinv*h (bf16)
__device__ float g_bufB[(size_t)N_NODES * HID];            // gather1 out (fp32)
__device__ float g_pooled[N_GRAPHS * HID];
__device__ int   g_cntg[N_GRAPHS];

// ---------------- init ----------------
__global__ void k_zero() {
    int i = blockIdx.x * blockDim.x + threadIdx.x;
    if (i < N_NODES) { g_deg[i] = 0.f; g_cnt[i] = 0; }
    if (i < N_GRAPHS * HID) g_pooled[i] = 0.f;
    if (i < N_GRAPHS) g_cntg[i] = 0;
}

// ---------------- degree histogram ----------------
__global__ void k_hist(const int4* __restrict__ col4, const float4* __restrict__ wa4) {
    int i = blockIdx.x * blockDim.x + threadIdx.x;
    if (i >= N_EDGES / 4) return;
    int4   c = col4[i];
    float4 w = wa4[i];
    atomicAdd(&g_cnt[c.x], 1); atomicAdd(&g_deg[c.x], fabsf(w.x));
    atomicAdd(&g_cnt[c.y], 1); atomicAdd(&g_deg[c.y], fabsf(w.y));
    atomicAdd(&g_cnt[c.z], 1); atomicAdd(&g_deg[c.z], fabsf(w.z));
    atomicAdd(&g_cnt[c.w], 1); atomicAdd(&g_deg[c.w], fabsf(w.w));
}

__global__ void k_dinv() {
    int i = blockIdx.x * blockDim.x + threadIdx.x;
    if (i < N_NODES) g_deg[i] = rsqrtf(g_deg[i] + 1.0f);
}

// ---------------- exclusive scan of g_cnt -> g_starts (+ seed cursor) ------
__global__ void k_scan1() {
    __shared__ int sh[SCAN_CHUNK];
    int idx = blockIdx.x * SCAN_CHUNK + threadIdx.x;
    sh[threadIdx.x] = (idx < N_NODES) ? g_cnt[idx] : 0;
    __syncthreads();
    for (int off = SCAN_CHUNK / 2; off > 0; off >>= 1) {
        if (threadIdx.x < off) sh[threadIdx.x] += sh[threadIdx.x + off];
        __syncthreads();
    }
    if (threadIdx.x == 0) g_bsum[blockIdx.x] = sh[0];
}

__global__ void k_scan2() {
    __shared__ int sh[128];
    int t = threadIdx.x;
    sh[t] = (t < NB) ? g_bsum[t] : 0;
    __syncthreads();
    if (t == 0) {
        int acc = 0;
        for (int b = 0; b < NB; b++) { int v = sh[b]; g_bsum[b] = acc; acc += v; }
        g_starts[N_NODES] = N_EDGES;
    }
}

__global__ void k_scan3() {
    __shared__ int sh[SCAN_CHUNK];
    int idx = blockIdx.x * SCAN_CHUNK + threadIdx.x;
    int v = (idx < N_NODES) ? g_cnt[idx] : 0;
    sh[threadIdx.x] = v;
    __syncthreads();
    for (int off = 1; off < SCAN_CHUNK; off <<= 1) {
        int t = (threadIdx.x >= off) ? sh[threadIdx.x - off] : 0;
        __syncthreads();
        sh[threadIdx.x] += t;
        __syncthreads();
    }
    if (idx < N_NODES) {
        int st = g_bsum[blockIdx.x] + sh[threadIdx.x] - v;
        g_starts[idx] = st;
        g_cursor[idx] = st;
    }
}

// ---------------- CSR fill (vectorized, 4 edges / thread) ------------------
__global__ void k_fill(const int4* __restrict__ row4, const int4* __restrict__ col4,
                       const float4* __restrict__ wa4) {
    int i = blockIdx.x * blockDim.x + threadIdx.x;
    if (i >= N_EDGES / 4) return;
    int4   r = row4[i];
    int4   c = col4[i];
    float4 w = wa4[i];
    int p;
    p = atomicAdd(&g_cursor[c.x], 1); g_edges[p] = make_int2(r.x, __float_as_int(fabsf(w.x)));
    p = atomicAdd(&g_cursor[c.y], 1); g_edges[p] = make_int2(r.y, __float_as_int(fabsf(w.y)));
    p = atomicAdd(&g_cursor[c.z], 1); g_edges[p] = make_int2(r.z, __float_as_int(fabsf(w.z)));
    p = atomicAdd(&g_cursor[c.w], 1); g_edges[p] = make_int2(r.w, __float_as_int(fabsf(w.w)));
}

// ---------------- fp32 SIMT GEMM ----------------
// BF16OUT=false: C[m,:] = A[m,:]@W                (raw, fp32 -> Cf)
// BF16OUT=true : g_hbf[m,:] = bf16(dinv[m] * (A[m,:]@W))
template <int K, bool BF16OUT>
__device__ __forceinline__ void gemm_impl(const float* __restrict__ A,
                                          const float* __restrict__ W,
                                          float* __restrict__ Cf) {
    __shared__ __align__(16) float xs[8][128];
    __shared__ __align__(16) float ws[8][64];
    const int M = N_NODES;
    int tid = threadIdx.x;
    int m0  = blockIdx.x * 128;
    int r0  = (tid >> 4) * 8;
    int c0  = (tid & 15) * 4;

    float4 acc[8];
#pragma unroll
    for (int i = 0; i < 8; i++) acc[i] = make_float4(0.f, 0.f, 0.f, 0.f);

    int ml = tid & 127;
    int kq = (tid >> 7) * 4;
    int mg = m0 + ml;
    const float* Arow = A + (size_t)mg * K;

    for (int k0 = 0; k0 < K; k0 += 8) {
        float4 xv = make_float4(0.f, 0.f, 0.f, 0.f);
        if (mg < M) xv = *(const float4*)(Arow + k0 + kq);
        if (tid < 128) {
            int kk = tid >> 4;
            int c  = (tid & 15) * 4;
            *(float4*)&ws[kk][c] = *(const float4*)(W + (k0 + kk) * 64 + c);
        }
        xs[kq + 0][ml] = xv.x;
        xs[kq + 1][ml] = xv.y;
        xs[kq + 2][ml] = xv.z;
        xs[kq + 3][ml] = xv.w;
        __syncthreads();
#pragma unroll
        for (int kk = 0; kk < 8; kk++) {
            float4 w4 = *(float4*)&ws[kk][c0];
            float4 a0 = *(float4*)&xs[kk][r0];
            float4 a1 = *(float4*)&xs[kk][r0 + 4];
            float a[8] = {a0.x, a0.y, a0.z, a0.w, a1.x, a1.y, a1.z, a1.w};
#pragma unroll
            for (int i = 0; i < 8; i++) {
                acc[i].x = fmaf(a[i], w4.x, acc[i].x);
                acc[i].y = fmaf(a[i], w4.y, acc[i].y);
                acc[i].z = fmaf(a[i], w4.z, acc[i].z);
                acc[i].w = fmaf(a[i], w4.w, acc[i].w);
            }
        }
        __syncthreads();
    }
#pragma unroll
    for (int i = 0; i < 8; i++) {
        int m = m0 + r0 + i;
        if (m < M) {
            float4 v = acc[i];
            if (BF16OUT) {
                float d = g_deg[m];
                __nv_bfloat162 lo = __float22bfloat162_rn(make_float2(v.x * d, v.y * d));
                __nv_bfloat162 hi = __float22bfloat162_rn(make_float2(v.z * d, v.w * d));
                __nv_bfloat162* dst = g_hbf + (size_t)m * (HID / 2) + (c0 >> 1);
                dst[0] = lo;
                dst[1] = hi;
            } else {
                *(float4*)(Cf + (size_t)m * 64 + c0) = v;
            }
        }
    }
}

__global__ void __launch_bounds__(256) k_gemm1(const float* __restrict__ x,
                                               const float* __restrict__ W1) {
    gemm_impl<IN_CH, false>(x, W1, g_bufA);    // raw x@W1 -> bufA (fp32)
}
__global__ void __launch_bounds__(256) k_gemm2(const float* __restrict__ W2) {
    gemm_impl<HID, true>(g_bufB, W2, nullptr); // dinv*(bufB@W2) -> g_hbf (bf16)
}

// ---------------- convert bufA -> bf16 h' with dinv scale -------------------
__global__ void k_conv() {
    int i = blockIdx.x * blockDim.x + threadIdx.x;   // one thread = 4 floats
    if (i >= N_NODES * 16) return;
    int n = i >> 4;
    float d = g_deg[n];
    float4 v = *(const float4*)(g_bufA + (size_t)i * 4);
    __nv_bfloat162 lo = __float22bfloat162_rn(make_float2(v.x * d, v.y * d));
    __nv_bfloat162 hi = __float22bfloat162_rn(make_float2(v.z * d, v.w * d));
    __nv_bfloat162* dst = g_hbf + (size_t)i * 2;
    dst[0] = lo;
    dst[1] = hi;
}

// --- warp-per-node gather: out = relu(dinv[n]*(sum w*h'[src] + h'[n]) + b) -
__global__ void __launch_bounds__(256) k_gather(const float* __restrict__ bias,
                                                const int* __restrict__ batch,
                                                int dopool) {
    int wid  = (blockIdx.x * blockDim.x + threadIdx.x) >> 5;
    int lane = threadIdx.x & 31;
    if (wid >= N_NODES) return;
    const __nv_bfloat162* __restrict__ h = g_hbf;
    int s = g_starts[wid];
    int e = g_starts[wid + 1];
    float ax = 0.f, ay = 0.f;
    for (int i = s; i < e; i += 32) {
        int rem = e - i;
        int2 ed = make_int2(0, 0);
        if (lane < rem) ed = g_edges[i + lane];
        int m = rem < 32 ? rem : 32;
#pragma unroll 4
        for (int j = 0; j < m; j++) {
            int   sj = __shfl_sync(0xffffffffu, ed.x, j);
            float wj = __int_as_float(__shfl_sync(0xffffffffu, ed.y, j));
            float2 hv = __bfloat1622float2(h[(size_t)sj * (HID / 2) + lane]);
            ax = fmaf(wj, hv.x, ax);
            ay = fmaf(wj, hv.y, ay);
        }
    }
    float2 hn = __bfloat1622float2(h[(size_t)wid * (HID / 2) + lane]);
    float d = g_deg[wid];
    int f = lane * 2;
    ax = fmaf(d, ax + hn.x, bias[f]);
    ay = fmaf(d, ay + hn.y, bias[f + 1]);
    ax = fmaxf(ax, 0.f);
    ay = fmaxf(ay, 0.f);
    if (!dopool) {
        *(float2*)(g_bufB + (size_t)wid * 64 + f) = make_float2(ax, ay);
    } else {
        int g = batch[wid];
        atomicAdd(&g_pooled[g * 64 + f],     ax);
        atomicAdd(&g_pooled[g * 64 + f + 1], ay);
        if (lane == 0) atomicAdd(&g_cntg[g], 1);
    }
}

// ---------------- final MLP ----------------
__global__ void __launch_bounds__(256) k_mlp(const float* __restrict__ L1,
                                             const float* __restrict__ c1,
                                             const float* __restrict__ L2,
                                             const float* __restrict__ c2,
                                             float* __restrict__ out) {
    int g = blockIdx.x;
    __shared__ float pm[HID];
    __shared__ float fea[IN_CH];
    __shared__ float red[256];
    int tid = threadIdx.x;
    if (tid < HID) {
        float cv = (float)g_cntg[g];
        pm[tid] = g_pooled[g * HID + tid] / fmaxf(cv, 1.0f);
    }
    __syncthreads();
    if (tid < IN_CH) {
        float s = c1[tid];
#pragma unroll
        for (int k = 0; k < HID; k++) s = fmaf(pm[k], L1[k * IN_CH + tid], s);
        fea[tid] = fmaxf(s, 0.f);
    }
    __syncthreads();
    float p0 = 0.f, p1 = 0.f;
    if (tid < IN_CH) {
        float fv = fea[tid];
        p0 = fv * L2[tid * OUT_CH];
        p1 = fv * L2[tid * OUT_CH + 1];
    }
    red[tid] = p0; __syncthreads();
    for (int off = 128; off > 0; off >>= 1) {
        if (tid < off) red[tid] += red[tid + off];
        __syncthreads();
    }
    float s0 = red[0];
    __syncthreads();
    red[tid] = p1; __syncthreads();
    for (int off = 128; off > 0; off >>= 1) {
        if (tid < off) red[tid] += red[tid + off];
        __syncthreads();
    }
    if (tid == 0) {
        out[g * OUT_CH]     = s0     + c2[0];
        out[g * OUT_CH + 1] = red[0] + c2[1];
    }
}

// ---------------- launch ----------------
extern "C" void kernel_launch(void* const* d_in, const int* in_sizes, int n_in,
                              void* d_out, int out_size) {
    const float* x         = (const float*)d_in[0];
    const int*   edge_idx  = (const int*)d_in[1];
    const float* edge_attr = (const float*)d_in[2];
    const int*   batch     = (const int*)d_in[3];
    const float* W1        = (const float*)d_in[4];
    const float* b1        = (const float*)d_in[5];
    const float* W2        = (const float*)d_in[6];
    const float* b2        = (const float*)d_in[7];
    const float* L1        = (const float*)d_in[8];
    const float* c1        = (const float*)d_in[9];
    const float* L2        = (const float*)d_in[10];
    const float* c2        = (const float*)d_in[11];
    float* out = (float*)d_out;

    const int* row = edge_idx;
    const int* col = edge_idx + N_EDGES;

    static cudaStream_t s2 = nullptr;
    static cudaEvent_t  evF = nullptr, evD = nullptr, evJ = nullptr;
    if (s2 == nullptr) {
        cudaStreamCreateWithFlags(&s2, cudaStreamNonBlocking);
        cudaEventCreateWithFlags(&evF, cudaEventDisableTiming);
        cudaEventCreateWithFlags(&evD, cudaEventDisableTiming);
        cudaEventCreateWithFlags(&evJ, cudaEventDisableTiming);
    }

    const int TB = 256;
    int nodeBlocks   = (N_NODES + TB - 1) / TB;
    int edge4Blocks  = (N_EDGES / 4 + TB - 1) / TB;
    int gemmBlocks   = (N_NODES + 127) / 128;
    int gatherBlocks = (N_NODES * 32 + TB - 1) / TB;
    int convBlocks   = (N_NODES * 16 + TB - 1) / TB;

    // fork immediately: GEMM1 raw has no dependencies
    cudaEventRecord(evF, 0);
    cudaStreamWaitEvent(s2, evF, 0);
    k_gemm1<<<gemmBlocks, 256, 0, s2>>>(x, W1);      // bufA = x @ W1 (raw)

    k_zero<<<nodeBlocks, TB>>>();
    k_hist<<<edge4Blocks, TB>>>((const int4*)col, (const float4*)edge_attr);
    k_dinv<<<nodeBlocks, TB>>>();
    cudaEventRecord(evD, 0);                          // dinv ready

    // s2: convert raw gemm1 out -> bf16 h' (needs dinv + gemm1)
    cudaStreamWaitEvent(s2, evD, 0);
    k_conv<<<convBlocks, TB, 0, s2>>>();
    cudaEventRecord(evJ, s2);

    k_scan1<<<NB, SCAN_CHUNK>>>();
    k_scan2<<<1, 128>>>();
    k_scan3<<<NB, SCAN_CHUNK>>>();
    k_fill<<<edge4Blocks, TB>>>((const int4*)row, (const int4*)col,
                                (const float4*)edge_attr);

    cudaStreamWaitEvent(0, evJ, 0);                   // join

    k_gather<<<gatherBlocks, TB>>>(b1, batch, 0);     // bufB = layer1 out (fp32)
    k_gemm2<<<gemmBlocks, 256>>>(W2);                 // g_hbf = bf16(dinv*(bufB@W2))
    k_gather<<<gatherBlocks, TB>>>(b2, batch, 1);     // pooling
    k_mlp<<<N_GRAPHS, 256>>>(L1, c1, L2, c2, out);
}

// round 4
// speedup vs baseline: 1.2664x; 1.0678x over previous
#include <cuda_runtime.h>
#include <cuda_bf16.h>
#include <math.h>

#define N_NODES   100000
#define N_EDGES   3200000
#define IN_CH     200
#define HID       64
#define N_GRAPHS  500
#define OUT_CH    2

#define SCAN_CHUNK 1024
#define NB ((N_NODES + SCAN_CHUNK - 1) / SCAN_CHUNK)   // 98

// ---------------- scratch ----------------
__device__ unsigned long long g_degcnt[N_NODES]; // {cnt<<40 | fx16 sum|w|}
__device__ float g_deg[N_NODES];                 // dinv
__device__ int   g_cnt[N_NODES];
__device__ int   g_cursor[N_NODES];
__device__ int   g_starts[N_NODES + 1];
__device__ int   g_bsum[128];
__device__ int2  g_edges[N_EDGES];               // {src, |w| bits}
__device__ float g_bufA[(size_t)N_NODES * HID];             // raw x@W1, later t
__device__ __nv_bfloat162 g_hbf [(size_t)N_NODES * (HID/2)];// dinv*(x@W1)
__device__ __nv_bfloat162 g_hbf2[(size_t)N_NODES * (HID/2)];// dinv*relu1
__device__ float g_pooled[N_GRAPHS * HID];
__device__ int   g_cntg[N_GRAPHS];

// ---------------- init ----------------
__global__ void k_zero() {
    int i = blockIdx.x * blockDim.x + threadIdx.x;
    if (i < N_NODES) g_degcnt[i] = 0ULL;
    if (i < N_GRAPHS * HID) g_pooled[i] = 0.f;
    if (i < N_GRAPHS) g_cntg[i] = 0;
}

__global__ void k_cntg(const int* __restrict__ batch) {
    int i = blockIdx.x * blockDim.x + threadIdx.x;
    if (i < N_NODES) atomicAdd(&g_cntg[batch[i]], 1);
}

// ---------------- packed degree histogram (1 atomic / edge) ----------------
__global__ void k_hist(const int4* __restrict__ col4, const float4* __restrict__ wa4) {
    int i = blockIdx.x * blockDim.x + threadIdx.x;
    if (i >= N_EDGES / 4) return;
    int4   c = col4[i];
    float4 w = wa4[i];
    const unsigned long long ONE = 1ULL << 40;
    atomicAdd(&g_degcnt[c.x], ONE + (unsigned long long)(fabsf(w.x) * 65536.0f + 0.5f));
    atomicAdd(&g_degcnt[c.y], ONE + (unsigned long long)(fabsf(w.y) * 65536.0f + 0.5f));
    atomicAdd(&g_degcnt[c.z], ONE + (unsigned long long)(fabsf(w.z) * 65536.0f + 0.5f));
    atomicAdd(&g_degcnt[c.w], ONE + (unsigned long long)(fabsf(w.w) * 65536.0f + 0.5f));
}

__global__ void k_dinv() {
    int i = blockIdx.x * blockDim.x + threadIdx.x;
    if (i >= N_NODES) return;
    unsigned long long v = g_degcnt[i];
    g_cnt[i] = (int)(v >> 40);
    float deg = (float)((double)(v & ((1ULL << 40) - 1)) * (1.0 / 65536.0));
    g_deg[i] = rsqrtf(deg + 1.0f);
}

// ---------------- exclusive scan ----------------
__global__ void k_scan1() {
    __shared__ int sh[SCAN_CHUNK];
    int idx = blockIdx.x * SCAN_CHUNK + threadIdx.x;
    sh[threadIdx.x] = (idx < N_NODES) ? g_cnt[idx] : 0;
    __syncthreads();
    for (int off = SCAN_CHUNK / 2; off > 0; off >>= 1) {
        if (threadIdx.x < off) sh[threadIdx.x] += sh[threadIdx.x + off];
        __syncthreads();
    }
    if (threadIdx.x == 0) g_bsum[blockIdx.x] = sh[0];
}

__global__ void k_scan2() {
    __shared__ int sh[128];
    int t = threadIdx.x;
    sh[t] = (t < NB) ? g_bsum[t] : 0;
    __syncthreads();
    if (t == 0) {
        int acc = 0;
        for (int b = 0; b < NB; b++) { int v = sh[b]; g_bsum[b] = acc; acc += v; }
        g_starts[N_NODES] = N_EDGES;
    }
}

__global__ void k_scan3() {
    __shared__ int sh[SCAN_CHUNK];
    int idx = blockIdx.x * SCAN_CHUNK + threadIdx.x;
    int v = (idx < N_NODES) ? g_cnt[idx] : 0;
    sh[threadIdx.x] = v;
    __syncthreads();
    for (int off = 1; off < SCAN_CHUNK; off <<= 1) {
        int t = (threadIdx.x >= off) ? sh[threadIdx.x - off] : 0;
        __syncthreads();
        sh[threadIdx.x] += t;
        __syncthreads();
    }
    if (idx < N_NODES) {
        int st = g_bsum[blockIdx.x] + sh[threadIdx.x] - v;
        g_starts[idx] = st;
        g_cursor[idx] = st;
    }
}

// ---------------- CSR fill ----------------
__global__ void k_fill(const int4* __restrict__ row4, const int4* __restrict__ col4,
                       const float4* __restrict__ wa4) {
    int i = blockIdx.x * blockDim.x + threadIdx.x;
    if (i >= N_EDGES / 4) return;
    int4   r = row4[i];
    int4   c = col4[i];
    float4 w = wa4[i];
    int p;
    p = atomicAdd(&g_cursor[c.x], 1); g_edges[p] = make_int2(r.x, __float_as_int(fabsf(w.x)));
    p = atomicAdd(&g_cursor[c.y], 1); g_edges[p] = make_int2(r.y, __float_as_int(fabsf(w.y)));
    p = atomicAdd(&g_cursor[c.z], 1); g_edges[p] = make_int2(r.z, __float_as_int(fabsf(w.z)));
    p = atomicAdd(&g_cursor[c.w], 1); g_edges[p] = make_int2(r.w, __float_as_int(fabsf(w.w)));
}

// ---------------- fp32 SIMT GEMM core ----------------
// POOL=false: C[m,:] = A[m,:]@W (raw fp32)
// POOL=true : pooled[batch[m]] += relu(A[m,:]@W + b)   (no C write)
template <int K, bool POOL>
__device__ __forceinline__ void gemm_impl(const float* __restrict__ A,
                                          const float* __restrict__ W,
                                          float* __restrict__ Cf,
                                          const float* __restrict__ bias,
                                          const int* __restrict__ batch) {
    __shared__ __align__(16) float xs[8][128];
    __shared__ __align__(16) float ws[8][64];
    const int M = N_NODES;
    int tid = threadIdx.x;
    int m0  = blockIdx.x * 128;
    int r0  = (tid >> 4) * 8;
    int c0  = (tid & 15) * 4;

    float4 acc[8];
#pragma unroll
    for (int i = 0; i < 8; i++) acc[i] = make_float4(0.f, 0.f, 0.f, 0.f);

    int ml = tid & 127;
    int kq = (tid >> 7) * 4;
    int mg = m0 + ml;
    const float* Arow = A + (size_t)mg * K;

    for (int k0 = 0; k0 < K; k0 += 8) {
        float4 xv = make_float4(0.f, 0.f, 0.f, 0.f);
        if (mg < M) xv = *(const float4*)(Arow + k0 + kq);
        if (tid < 128) {
            int kk = tid >> 4;
            int c  = (tid & 15) * 4;
            *(float4*)&ws[kk][c] = *(const float4*)(W + (k0 + kk) * 64 + c);
        }
        xs[kq + 0][ml] = xv.x;
        xs[kq + 1][ml] = xv.y;
        xs[kq + 2][ml] = xv.z;
        xs[kq + 3][ml] = xv.w;
        __syncthreads();
#pragma unroll
        for (int kk = 0; kk < 8; kk++) {
            float4 w4 = *(float4*)&ws[kk][c0];
            float4 a0 = *(float4*)&xs[kk][r0];
            float4 a1 = *(float4*)&xs[kk][r0 + 4];
            float a[8] = {a0.x, a0.y, a0.z, a0.w, a1.x, a1.y, a1.z, a1.w};
#pragma unroll
            for (int i = 0; i < 8; i++) {
                acc[i].x = fmaf(a[i], w4.x, acc[i].x);
                acc[i].y = fmaf(a[i], w4.y, acc[i].y);
                acc[i].z = fmaf(a[i], w4.z, acc[i].z);
                acc[i].w = fmaf(a[i], w4.w, acc[i].w);
            }
        }
        __syncthreads();
    }
    float4 bv = make_float4(0.f, 0.f, 0.f, 0.f);
    if (POOL) bv = *(const float4*)(bias + c0);
#pragma unroll
    for (int i = 0; i < 8; i++) {
        int m = m0 + r0 + i;
        if (m < M) {
            float4 v = acc[i];
            if (POOL) {
                v.x = fmaxf(v.x + bv.x, 0.f);
                v.y = fmaxf(v.y + bv.y, 0.f);
                v.z = fmaxf(v.z + bv.z, 0.f);
                v.w = fmaxf(v.w + bv.w, 0.f);
                int g = batch[m];
                float* dst = g_pooled + g * 64 + c0;
#if __CUDA_ARCH__ >= 900
                atomicAdd((float4*)dst, v);
#else
                atomicAdd(dst + 0, v.x);
                atomicAdd(dst + 1, v.y);
                atomicAdd(dst + 2, v.z);
                atomicAdd(dst + 3, v.w);
#endif
            } else {
                *(float4*)(Cf + (size_t)m * 64 + c0) = v;
            }
        }
    }
}

__global__ void __launch_bounds__(256) k_gemm1(const float* __restrict__ x,
                                               const float* __restrict__ W1) {
    gemm_impl<IN_CH, false>(x, W1, g_bufA, nullptr, nullptr);
}
__global__ void __launch_bounds__(256) k_gemm2pool(const float* __restrict__ W2,
                                                   const float* __restrict__ b2,
                                                   const int* __restrict__ batch) {
    gemm_impl<HID, true>(g_bufA, W2, nullptr, b2, batch);
}

// ---------------- convert bufA -> bf16 with dinv scale ----------------
__global__ void k_conv() {
    int i = blockIdx.x * blockDim.x + threadIdx.x;   // 4 floats / thread
    if (i >= N_NODES * 16) return;
    int n = i >> 4;
    float d = g_deg[n];
    float4 v = *(const float4*)(g_bufA + (size_t)i * 4);
    __nv_bfloat162 lo = __float22bfloat162_rn(make_float2(v.x * d, v.y * d));
    __nv_bfloat162 hi = __float22bfloat162_rn(make_float2(v.z * d, v.w * d));
    __nv_bfloat162* dst = g_hbf + (size_t)i * 2;
    dst[0] = lo;
    dst[1] = hi;
}

// ---- gather, uniform edge loads (no shfl): all lanes read g_edges[i] ------
// layer 1: g_hbf2[n] = bf16( dinv[n] * relu( dinv[n]*(sum + hn) + b1 ) )
__global__ void __launch_bounds__(256) k_gather1(const float* __restrict__ bias) {
    int wid  = (blockIdx.x * blockDim.x + threadIdx.x) >> 5;
    int lane = threadIdx.x & 31;
    if (wid >= N_NODES) return;
    const __nv_bfloat162* __restrict__ h = g_hbf;
    int s = g_starts[wid];
    int e = g_starts[wid + 1];
    float ax = 0.f, ay = 0.f;
#pragma unroll 8
    for (int i = s; i < e; i++) {
        int2 ed = g_edges[i];                        // uniform across warp
        float w = __int_as_float(ed.y);
        float2 hv = __bfloat1622float2(h[(size_t)ed.x * 32 + lane]);
        ax = fmaf(w, hv.x, ax);
        ay = fmaf(w, hv.y, ay);
    }
    float2 hn = __bfloat1622float2(h[(size_t)wid * 32 + lane]);
    float d = g_deg[wid];
    int f = lane * 2;
    ax = fmaf(d, ax + hn.x, bias[f]);
    ay = fmaf(d, ay + hn.y, bias[f + 1]);
    ax = fmaxf(ax, 0.f) * d;
    ay = fmaxf(ay, 0.f) * d;
    g_hbf2[(size_t)wid * 32 + lane] = __float22bfloat162_rn(make_float2(ax, ay));
}

// layer 2 aggregation: g_bufA[n,:] = dinv[n]*(sum w*h2[src] + h2[n])  (fp32)
__global__ void __launch_bounds__(256) k_gather2() {
    int wid  = (blockIdx.x * blockDim.x + threadIdx.x) >> 5;
    int lane = threadIdx.x & 31;
    if (wid >= N_NODES) return;
    const __nv_bfloat162* __restrict__ h = g_hbf2;
    int s = g_starts[wid];
    int e = g_starts[wid + 1];
    float ax = 0.f, ay = 0.f;
#pragma unroll 8
    for (int i = s; i < e; i++) {
        int2 ed = g_edges[i];
        float w = __int_as_float(ed.y);
        float2 hv = __bfloat1622float2(h[(size_t)ed.x * 32 + lane]);
        ax = fmaf(w, hv.x, ax);
        ay = fmaf(w, hv.y, ay);
    }
    float2 hn = __bfloat1622float2(h[(size_t)wid * 32 + lane]);
    float d = g_deg[wid];
    *(float2*)(g_bufA + (size_t)wid * 64 + lane * 2) =
        make_float2(d * (ax + hn.x), d * (ay + hn.y));
}

// ---------------- final MLP ----------------
__global__ void __launch_bounds__(256) k_mlp(const float* __restrict__ L1,
                                             const float* __restrict__ c1,
                                             const float* __restrict__ L2,
                                             const float* __restrict__ c2,
                                             float* __restrict__ out) {
    int g = blockIdx.x;
    __shared__ float pm[HID];
    __shared__ float fea[IN_CH];
    __shared__ float red[256];
    int tid = threadIdx.x;
    if (tid < HID) {
        float cv = (float)g_cntg[g];
        pm[tid] = g_pooled[g * HID + tid] / fmaxf(cv, 1.0f);
    }
    __syncthreads();
    if (tid < IN_CH) {
        float s = c1[tid];
#pragma unroll
        for (int k = 0; k < HID; k++) s = fmaf(pm[k], L1[k * IN_CH + tid], s);
        fea[tid] = fmaxf(s, 0.f);
    }
    __syncthreads();
    float p0 = 0.f, p1 = 0.f;
    if (tid < IN_CH) {
        float fv = fea[tid];
        p0 = fv * L2[tid * OUT_CH];
        p1 = fv * L2[tid * OUT_CH + 1];
    }
    red[tid] = p0; __syncthreads();
    for (int off = 128; off > 0; off >>= 1) {
        if (tid < off) red[tid] += red[tid + off];
        __syncthreads();
    }
    float s0 = red[0];
    __syncthreads();
    red[tid] = p1; __syncthreads();
    for (int off = 128; off > 0; off >>= 1) {
        if (tid < off) red[tid] += red[tid + off];
        __syncthreads();
    }
    if (tid == 0) {
        out[g * OUT_CH]     = s0     + c2[0];
        out[g * OUT_CH + 1] = red[0] + c2[1];
    }
}

// ---------------- launch ----------------
extern "C" void kernel_launch(void* const* d_in, const int* in_sizes, int n_in,
                              void* d_out, int out_size) {
    const float* x         = (const float*)d_in[0];
    const int*   edge_idx  = (const int*)d_in[1];
    const float* edge_attr = (const float*)d_in[2];
    const int*   batch     = (const int*)d_in[3];
    const float* W1        = (const float*)d_in[4];
    const float* b1        = (const float*)d_in[5];
    const float* W2        = (const float*)d_in[6];
    const float* b2        = (const float*)d_in[7];
    const float* L1        = (const float*)d_in[8];
    const float* c1        = (const float*)d_in[9];
    const float* L2        = (const float*)d_in[10];
    const float* c2        = (const float*)d_in[11];
    float* out = (float*)d_out;

    const int* row = edge_idx;
    const int* col = edge_idx + N_EDGES;

    static cudaStream_t s2 = nullptr;
    static cudaEvent_t  evF = nullptr, evD = nullptr, evJ = nullptr;
    if (s2 == nullptr) {
        cudaStreamCreateWithFlags(&s2, cudaStreamNonBlocking);
        cudaEventCreateWithFlags(&evF, cudaEventDisableTiming);
        cudaEventCreateWithFlags(&evD, cudaEventDisableTiming);
        cudaEventCreateWithFlags(&evJ, cudaEventDisableTiming);
    }

    const int TB = 256;
    int nodeBlocks   = (N_NODES + TB - 1) / TB;
    int edge4Blocks  = (N_EDGES / 4 + TB - 1) / TB;
    int gemmBlocks   = (N_NODES + 127) / 128;
    int gatherBlocks = (N_NODES * 32 + TB - 1) / TB;
    int convBlocks   = (N_NODES * 16 + TB - 1) / TB;

    // fork: GEMM1 raw has no dependencies
    cudaEventRecord(evF, 0);
    cudaStreamWaitEvent(s2, evF, 0);
    k_gemm1<<<gemmBlocks, 256, 0, s2>>>(x, W1);      // bufA = x @ W1 (raw)

    k_zero<<<nodeBlocks, TB>>>();
    k_cntg<<<nodeBlocks, TB>>>(batch);
    k_hist<<<edge4Blocks, TB>>>((const int4*)col, (const float4*)edge_attr);
    k_dinv<<<nodeBlocks, TB>>>();
    cudaEventRecord(evD, 0);                          // dinv ready

    cudaStreamWaitEvent(s2, evD, 0);
    k_conv<<<convBlocks, TB, 0, s2>>>();              // g_hbf = bf16(dinv*bufA)
    cudaEventRecord(evJ, s2);

    k_scan1<<<NB, SCAN_CHUNK>>>();
    k_scan2<<<1, 128>>>();
    k_scan3<<<NB, SCAN_CHUNK>>>();
    k_fill<<<edge4Blocks, TB>>>((const int4*)row, (const int4*)col,
                                (const float4*)edge_attr);

    cudaStreamWaitEvent(0, evJ, 0);                   // join

    k_gather1<<<gatherBlocks, TB>>>(b1);              // g_hbf2 = dinv*relu1 (bf16)
    k_gather2<<<gatherBlocks, TB>>>();                // bufA = t (fp32)
    k_gemm2pool<<<gemmBlocks, 256>>>(W2, b2, batch);  // pooled += relu(t@W2+b2)
    k_mlp<<<N_GRAPHS, 256>>>(L1, c1, L2, c2, out);
}

// round 6
// speedup vs baseline: 1.3489x; 1.0652x over previous
#include <cuda_runtime.h>
#include <cuda_bf16.h>
#include <math.h>
#include <string.h>

#define N_NODES   100000
#define N_EDGES   3200000
#define IN_CH     200
#define HID       64
#define N_GRAPHS  500
#define OUT_CH    2

#define SCAN_CHUNK 1024
#define NB ((N_NODES + SCAN_CHUNK - 1) / SCAN_CHUNK)   // 98

__device__ __forceinline__ unsigned int bf2_bits(__nv_bfloat162 v) {
    unsigned int u;
    memcpy(&u, &v, 4);
    return u;
}

// ---------------- scratch ----------------
__device__ unsigned long long g_degcnt[N_NODES]; // {cnt<<40 | fx16 sum|w|}
__device__ float g_deg[N_NODES];                 // dinv
__device__ int   g_cnt[N_NODES];
__device__ int   g_cursor[N_NODES];
__device__ int   g_starts[N_NODES + 1];
__device__ int   g_bsum[128];
__device__ int2  g_edges[N_EDGES];               // {src, |w| bits}
__device__ float g_bufA[(size_t)N_NODES * HID];  // raw x@W1, later t
__device__ uint4 g_hbf [(size_t)N_NODES * 8];    // bf16 h' rows (128B/row)
__device__ uint4 g_hbf2[(size_t)N_NODES * 8];    // bf16 dinv*relu1 rows
__device__ float g_pooled[N_GRAPHS * HID];
__device__ int   g_cntg[N_GRAPHS];

// ---------------- init ----------------
__global__ void k_zero() {
    int i = blockIdx.x * blockDim.x + threadIdx.x;
    if (i < N_NODES) g_degcnt[i] = 0ULL;
    if (i < N_GRAPHS * HID) g_pooled[i] = 0.f;
    if (i < N_GRAPHS) g_cntg[i] = 0;
}

__global__ void k_cntg(const int* __restrict__ batch) {
    int i = blockIdx.x * blockDim.x + threadIdx.x;
    if (i < N_NODES) atomicAdd(&g_cntg[batch[i]], 1);
}

// ---------------- packed degree histogram (1 atomic / edge) ----------------
__global__ void k_hist(const int4* __restrict__ col4, const float4* __restrict__ wa4) {
    int i = blockIdx.x * blockDim.x + threadIdx.x;
    if (i >= N_EDGES / 4) return;
    int4   c = col4[i];
    float4 w = wa4[i];
    const unsigned long long ONE = 1ULL << 40;
    atomicAdd(&g_degcnt[c.x], ONE + (unsigned long long)(fabsf(w.x) * 65536.0f + 0.5f));
    atomicAdd(&g_degcnt[c.y], ONE + (unsigned long long)(fabsf(w.y) * 65536.0f + 0.5f));
    atomicAdd(&g_degcnt[c.z], ONE + (unsigned long long)(fabsf(w.z) * 65536.0f + 0.5f));
    atomicAdd(&g_degcnt[c.w], ONE + (unsigned long long)(fabsf(w.w) * 65536.0f + 0.5f));
}

__global__ void k_dinv() {
    int i = blockIdx.x * blockDim.x + threadIdx.x;
    if (i >= N_NODES) return;
    unsigned long long v = g_degcnt[i];
    g_cnt[i] = (int)(v >> 40);
    float deg = (float)((double)(v & ((1ULL << 40) - 1)) * (1.0 / 65536.0));
    g_deg[i] = rsqrtf(deg + 1.0f);
}

// ---------------- exclusive scan ----------------
__global__ void k_scan1() {
    __shared__ int sh[SCAN_CHUNK];
    int idx = blockIdx.x * SCAN_CHUNK + threadIdx.x;
    sh[threadIdx.x] = (idx < N_NODES) ? g_cnt[idx] : 0;
    __syncthreads();
    for (int off = SCAN_CHUNK / 2; off > 0; off >>= 1) {
        if (threadIdx.x < off) sh[threadIdx.x] += sh[threadIdx.x + off];
        __syncthreads();
    }
    if (threadIdx.x == 0) g_bsum[blockIdx.x] = sh[0];
}

__global__ void k_scan2() {
    __shared__ int sh[128];
    int t = threadIdx.x;
    sh[t] = (t < NB) ? g_bsum[t] : 0;
    __syncthreads();
    if (t == 0) {
        int acc = 0;
        for (int b = 0; b < NB; b++) { int v = sh[b]; g_bsum[b] = acc; acc += v; }
        g_starts[N_NODES] = N_EDGES;
    }
}

__global__ void k_scan3() {
    __shared__ int sh[SCAN_CHUNK];
    int idx = blockIdx.x * SCAN_CHUNK + threadIdx.x;
    int v = (idx < N_NODES) ? g_cnt[idx] : 0;
    sh[threadIdx.x] = v;
    __syncthreads();
    for (int off = 1; off < SCAN_CHUNK; off <<= 1) {
        int t = (threadIdx.x >= off) ? sh[threadIdx.x - off] : 0;
        __syncthreads();
        sh[threadIdx.x] += t;
        __syncthreads();
    }
    if (idx < N_NODES) {
        int st = g_bsum[blockIdx.x] + sh[threadIdx.x] - v;
        g_starts[idx] = st;
        g_cursor[idx] = st;
    }
}

// ---------------- CSR fill ----------------
__global__ void k_fill(const int4* __restrict__ row4, const int4* __restrict__ col4,
                       const float4* __restrict__ wa4) {
    int i = blockIdx.x * blockDim.x + threadIdx.x;
    if (i >= N_EDGES / 4) return;
    int4   r = row4[i];
    int4   c = col4[i];
    float4 w = wa4[i];
    int p;
    p = atomicAdd(&g_cursor[c.x], 1); g_edges[p] = make_int2(r.x, __float_as_int(fabsf(w.x)));
    p = atomicAdd(&g_cursor[c.y], 1); g_edges[p] = make_int2(r.y, __float_as_int(fabsf(w.y)));
    p = atomicAdd(&g_cursor[c.z], 1); g_edges[p] = make_int2(r.z, __float_as_int(fabsf(w.z)));
    p = atomicAdd(&g_cursor[c.w], 1); g_edges[p] = make_int2(r.w, __float_as_int(fabsf(w.w)));
}

// ---------------- fp32 SIMT GEMM core ----------------
template <int K, bool POOL>
__device__ __forceinline__ void gemm_impl(const float* __restrict__ A,
                                          const float* __restrict__ W,
                                          float* __restrict__ Cf,
                                          const float* __restrict__ bias,
                                          const int* __restrict__ batch) {
    __shared__ __align__(16) float xs[8][128];
    __shared__ __align__(16) float ws[8][64];
    const int M = N_NODES;
    int tid = threadIdx.x;
    int m0  = blockIdx.x * 128;
    int r0  = (tid >> 4) * 8;
    int c0  = (tid & 15) * 4;

    float4 acc[8];
#pragma unroll
    for (int i = 0; i < 8; i++) acc[i] = make_float4(0.f, 0.f, 0.f, 0.f);

    int ml = tid & 127;
    int kq = (tid >> 7) * 4;
    int mg = m0 + ml;
    const float* Arow = A + (size_t)mg * K;

    for (int k0 = 0; k0 < K; k0 += 8) {
        float4 xv = make_float4(0.f, 0.f, 0.f, 0.f);
        if (mg < M) xv = *(const float4*)(Arow + k0 + kq);
        if (tid < 128) {
            int kk = tid >> 4;
            int c  = (tid & 15) * 4;
            *(float4*)&ws[kk][c] = *(const float4*)(W + (k0 + kk) * 64 + c);
        }
        xs[kq + 0][ml] = xv.x;
        xs[kq + 1][ml] = xv.y;
        xs[kq + 2][ml] = xv.z;
        xs[kq + 3][ml] = xv.w;
        __syncthreads();
#pragma unroll
        for (int kk = 0; kk < 8; kk++) {
            float4 w4 = *(float4*)&ws[kk][c0];
            float4 a0 = *(float4*)&xs[kk][r0];
            float4 a1 = *(float4*)&xs[kk][r0 + 4];
            float a[8] = {a0.x, a0.y, a0.z, a0.w, a1.x, a1.y, a1.z, a1.w};
#pragma unroll
            for (int i = 0; i < 8; i++) {
                acc[i].x = fmaf(a[i], w4.x, acc[i].x);
                acc[i].y = fmaf(a[i], w4.y, acc[i].y);
                acc[i].z = fmaf(a[i], w4.z, acc[i].z);
                acc[i].w = fmaf(a[i], w4.w, acc[i].w);
            }
        }
        __syncthreads();
    }
    float4 bv = make_float4(0.f, 0.f, 0.f, 0.f);
    if (POOL) bv = *(const float4*)(bias + c0);
#pragma unroll
    for (int i = 0; i < 8; i++) {
        int m = m0 + r0 + i;
        if (m < M) {
            float4 v = acc[i];
            if (POOL) {
                v.x = fmaxf(v.x + bv.x, 0.f);
                v.y = fmaxf(v.y + bv.y, 0.f);
                v.z = fmaxf(v.z + bv.z, 0.f);
                v.w = fmaxf(v.w + bv.w, 0.f);
                int g = batch[m];
                float* dst = g_pooled + g * 64 + c0;
#if __CUDA_ARCH__ >= 900
                atomicAdd((float4*)dst, v);
#else
                atomicAdd(dst + 0, v.x);
                atomicAdd(dst + 1, v.y);
                atomicAdd(dst + 2, v.z);
                atomicAdd(dst + 3, v.w);
#endif
            } else {
                *(float4*)(Cf + (size_t)m * 64 + c0) = v;
            }
        }
    }
}

__global__ void __launch_bounds__(256) k_gemm1(const float* __restrict__ x,
                                               const float* __restrict__ W1) {
    gemm_impl<IN_CH, false>(x, W1, g_bufA, nullptr, nullptr);
}
__global__ void __launch_bounds__(256) k_gemm2pool(const float* __restrict__ W2,
                                                   const float* __restrict__ b2,
                                                   const int* __restrict__ batch) {
    gemm_impl<HID, true>(g_bufA, W2, nullptr, b2, batch);
}

// ---------------- convert bufA -> bf16 with dinv scale ----------------
__global__ void k_conv() {
    int i = blockIdx.x * blockDim.x + threadIdx.x;   // one uint4 (8 feats) / thread
    if (i >= N_NODES * 8) return;
    int n = i >> 3;
    float d = g_deg[n];
    const float* src = g_bufA + (size_t)i * 8;
    float4 v0 = *(const float4*)(src);
    float4 v1 = *(const float4*)(src + 4);
    uint4 o;
    o.x = bf2_bits(__float22bfloat162_rn(make_float2(v0.x * d, v0.y * d)));
    o.y = bf2_bits(__float22bfloat162_rn(make_float2(v0.z * d, v0.w * d)));
    o.z = bf2_bits(__float22bfloat162_rn(make_float2(v1.x * d, v1.y * d)));
    o.w = bf2_bits(__float22bfloat162_rn(make_float2(v1.z * d, v1.w * d)));
    g_hbf[i] = o;
}

// ---- 4-edges-per-warp gather: 8 lanes/edge, 0.5 LDG per edge --------------
// eg = lane>>3 (edge slot), fl = lane&7 (feature group: feats fl*8..fl*8+7)
__device__ __forceinline__ void gather_core(const uint4* __restrict__ h,
                                            int s, int e, int eg, int fl,
                                            float acc[8]) {
#pragma unroll 2
    for (int i = s; i < e; i += 4) {
        int idx = i + eg;
        int cl  = idx < e ? idx : (e - 1);
        int2 ed = g_edges[cl];
        float w = idx < e ? __int_as_float(ed.y) : 0.f;
        uint4 hv = h[(size_t)ed.x * 8 + fl];
        float2 p0 = __bfloat1622float2(*(__nv_bfloat162*)&hv.x);
        float2 p1 = __bfloat1622float2(*(__nv_bfloat162*)&hv.y);
        float2 p2 = __bfloat1622float2(*(__nv_bfloat162*)&hv.z);
        float2 p3 = __bfloat1622float2(*(__nv_bfloat162*)&hv.w);
        acc[0] = fmaf(w, p0.x, acc[0]);
        acc[1] = fmaf(w, p0.y, acc[1]);
        acc[2] = fmaf(w, p1.x, acc[2]);
        acc[3] = fmaf(w, p1.y, acc[3]);
        acc[4] = fmaf(w, p2.x, acc[4]);
        acc[5] = fmaf(w, p2.y, acc[5]);
        acc[6] = fmaf(w, p3.x, acc[6]);
        acc[7] = fmaf(w, p3.y, acc[7]);
    }
#pragma unroll
    for (int k = 0; k < 8; k++) {
        acc[k] += __shfl_xor_sync(0xffffffffu, acc[k], 8);
        acc[k] += __shfl_xor_sync(0xffffffffu, acc[k], 16);
    }
}

// layer 1: g_hbf2[n] = bf16( dinv * relu( dinv*(sum + hn) + b1 ) )
__global__ void __launch_bounds__(256) k_gather1(const float* __restrict__ bias) {
    int wid  = (blockIdx.x * blockDim.x + threadIdx.x) >> 5;
    int lane = threadIdx.x & 31;
    if (wid >= N_NODES) return;
    int s = g_starts[wid];
    int e = g_starts[wid + 1];
    int eg = lane >> 3;
    int fl = lane & 7;
    float acc[8] = {0.f, 0.f, 0.f, 0.f, 0.f, 0.f, 0.f, 0.f};
    gather_core(g_hbf, s, e, eg, fl, acc);
    if (eg == 0) {
        uint4 hn = g_hbf[(size_t)wid * 8 + fl];
        float2 q0 = __bfloat1622float2(*(__nv_bfloat162*)&hn.x);
        float2 q1 = __bfloat1622float2(*(__nv_bfloat162*)&hn.y);
        float2 q2 = __bfloat1622float2(*(__nv_bfloat162*)&hn.z);
        float2 q3 = __bfloat1622float2(*(__nv_bfloat162*)&hn.w);
        float d = g_deg[wid];
        float4 bA = *(const float4*)(bias + fl * 8);
        float4 bB = *(const float4*)(bias + fl * 8 + 4);
        float o0 = fmaxf(fmaf(d, acc[0] + q0.x, bA.x), 0.f) * d;
        float o1 = fmaxf(fmaf(d, acc[1] + q0.y, bA.y), 0.f) * d;
        float o2 = fmaxf(fmaf(d, acc[2] + q1.x, bA.z), 0.f) * d;
        float o3 = fmaxf(fmaf(d, acc[3] + q1.y, bA.w), 0.f) * d;
        float o4 = fmaxf(fmaf(d, acc[4] + q2.x, bB.x), 0.f) * d;
        float o5 = fmaxf(fmaf(d, acc[5] + q2.y, bB.y), 0.f) * d;
        float o6 = fmaxf(fmaf(d, acc[6] + q3.x, bB.z), 0.f) * d;
        float o7 = fmaxf(fmaf(d, acc[7] + q3.y, bB.w), 0.f) * d;
        uint4 o;
        o.x = bf2_bits(__float22bfloat162_rn(make_float2(o0, o1)));
        o.y = bf2_bits(__float22bfloat162_rn(make_float2(o2, o3)));
        o.z = bf2_bits(__float22bfloat162_rn(make_float2(o4, o5)));
        o.w = bf2_bits(__float22bfloat162_rn(make_float2(o6, o7)));
        g_hbf2[(size_t)wid * 8 + fl] = o;
    }
}

// layer 2: g_bufA[n,:] = dinv*(sum + hn)   (fp32)
__global__ void __launch_bounds__(256) k_gather2() {
    int wid  = (blockIdx.x * blockDim.x + threadIdx.x) >> 5;
    int lane = threadIdx.x & 31;
    if (wid >= N_NODES) return;
    int s = g_starts[wid];
    int e = g_starts[wid + 1];
    int eg = lane >> 3;
    int fl = lane & 7;
    float acc[8] = {0.f, 0.f, 0.f, 0.f, 0.f, 0.f, 0.f, 0.f};
    gather_core(g_hbf2, s, e, eg, fl, acc);
    if (eg == 0) {
        uint4 hn = g_hbf2[(size_t)wid * 8 + fl];
        float2 q0 = __bfloat1622float2(*(__nv_bfloat162*)&hn.x);
        float2 q1 = __bfloat1622float2(*(__nv_bfloat162*)&hn.y);
        float2 q2 = __bfloat1622float2(*(__nv_bfloat162*)&hn.z);
        float2 q3 = __bfloat1622float2(*(__nv_bfloat162*)&hn.w);
        float d = g_deg[wid];
        float* dst = g_bufA + (size_t)wid * 64 + fl * 8;
        float4 oA, oB;
        oA.x = d * (acc[0] + q0.x);
        oA.y = d * (acc[1] + q0.y);
        oA.z = d * (acc[2] + q1.x);
        oA.w = d * (acc[3] + q1.y);
        oB.x = d * (acc[4] + q2.x);
        oB.y = d * (acc[5] + q2.y);
        oB.z = d * (acc[6] + q3.x);
        oB.w = d * (acc[7] + q3.y);
        *(float4*)(dst)     = oA;
        *(float4*)(dst + 4) = oB;
    }
}

// ---------------- final MLP ----------------
__global__ void __launch_bounds__(256) k_mlp(const float* __restrict__ L1,
                                             const float* __restrict__ c1,
                                             const float* __restrict__ L2,
                                             const float* __restrict__ c2,
                                             float* __restrict__ out) {
    int g = blockIdx.x;
    __shared__ float pm[HID];
    __shared__ float fea[IN_CH];
    __shared__ float red[256];
    int tid = threadIdx.x;
    if (tid < HID) {
        float cv = (float)g_cntg[g];
        pm[tid] = g_pooled[g * HID + tid] / fmaxf(cv, 1.0f);
    }
    __syncthreads();
    if (tid < IN_CH) {
        float s = c1[tid];
#pragma unroll
        for (int k = 0; k < HID; k++) s = fmaf(pm[k], L1[k * IN_CH + tid], s);
        fea[tid] = fmaxf(s, 0.f);
    }
    __syncthreads();
    float p0 = 0.f, p1 = 0.f;
    if (tid < IN_CH) {
        float fv = fea[tid];
        p0 = fv * L2[tid * OUT_CH];
        p1 = fv * L2[tid * OUT_CH + 1];
    }
    red[tid] = p0; __syncthreads();
    for (int off = 128; off > 0; off >>= 1) {
        if (tid < off) red[tid] += red[tid + off];
        __syncthreads();
    }
    float s0 = red[0];
    __syncthreads();
    red[tid] = p1; __syncthreads();
    for (int off = 128; off > 0; off >>= 1) {
        if (tid < off) red[tid] += red[tid + off];
        __syncthreads();
    }
    if (tid == 0) {
        out[g * OUT_CH]     = s0     + c2[0];
        out[g * OUT_CH + 1] = red[0] + c2[1];
    }
}

// ---------------- launch ----------------
extern "C" void kernel_launch(void* const* d_in, const int* in_sizes, int n_in,
                              void* d_out, int out_size) {
    const float* x         = (const float*)d_in[0];
    const int*   edge_idx  = (const int*)d_in[1];
    const float* edge_attr = (const float*)d_in[2];
    const int*   batch     = (const int*)d_in[3];
    const float* W1        = (const float*)d_in[4];
    const float* b1        = (const float*)d_in[5];
    const float* W2        = (const float*)d_in[6];
    const float* b2        = (const float*)d_in[7];
    const float* L1        = (const float*)d_in[8];
    const float* c1        = (const float*)d_in[9];
    const float* L2        = (const float*)d_in[10];
    const float* c2        = (const float*)d_in[11];
    float* out = (float*)d_out;

    const int* row = edge_idx;
    const int* col = edge_idx + N_EDGES;

    static cudaStream_t s2 = nullptr;
    static cudaEvent_t  evF = nullptr, evD = nullptr, evJ = nullptr;
    if (s2 == nullptr) {
        cudaStreamCreateWithFlags(&s2, cudaStreamNonBlocking);
        cudaEventCreateWithFlags(&evF, cudaEventDisableTiming);
        cudaEventCreateWithFlags(&evD, cudaEventDisableTiming);
        cudaEventCreateWithFlags(&evJ, cudaEventDisableTiming);
    }

    const int TB = 256;
    int nodeBlocks   = (N_NODES + TB - 1) / TB;
    int edge4Blocks  = (N_EDGES / 4 + TB - 1) / TB;
    int gemmBlocks   = (N_NODES + 127) / 128;
    int gatherBlocks = (N_NODES * 32 + TB - 1) / TB;
    int convBlocks   = (N_NODES * 8 + TB - 1) / TB;

    // fork: GEMM1 raw has no dependencies
    cudaEventRecord(evF, 0);
    cudaStreamWaitEvent(s2, evF, 0);
    k_gemm1<<<gemmBlocks, 256, 0, s2>>>(x, W1);      // bufA = x @ W1 (raw)

    k_zero<<<nodeBlocks, TB>>>();
    k_cntg<<<nodeBlocks, TB>>>(batch);
    k_hist<<<edge4Blocks, TB>>>((const int4*)col, (const float4*)edge_attr);
    k_dinv<<<nodeBlocks, TB>>>();
    cudaEventRecord(evD, 0);                          // dinv ready

    cudaStreamWaitEvent(s2, evD, 0);
    k_conv<<<convBlocks, TB, 0, s2>>>();              // g_hbf = bf16(dinv*bufA)
    cudaEventRecord(evJ, s2);

    k_scan1<<<NB, SCAN_CHUNK>>>();
    k_scan2<<<1, 128>>>();
    k_scan3<<<NB, SCAN_CHUNK>>>();
    k_fill<<<edge4Blocks, TB>>>((const int4*)row, (const int4*)col,
                                (const float4*)edge_attr);

    cudaStreamWaitEvent(0, evJ, 0);                   // join

    k_gather1<<<gatherBlocks, TB>>>(b1);              // g_hbf2 = dinv*relu1 (bf16)
    k_gather2<<<gatherBlocks, TB>>>();                // bufA = t (fp32)
    k_gemm2pool<<<gemmBlocks, 256>>>(W2, b2, batch);  // pooled += relu(t@W2+b2)
    k_mlp<<<N_GRAPHS, 256>>>(L1, c1, L2, c2, out);
}

// round 9
// speedup vs baseline: 1.4544x; 1.0782x over previous
#include <cuda_runtime.h>
#include <cuda_bf16.h>
#include <math.h>
#include <string.h>
#include <stdint.h>

typedef unsigned int       u32;
typedef unsigned long long u64;

#define N_NODES   100000
#define N_EDGES   3200000
#define IN_CH     200
#define HID       64
#define N_GRAPHS  500
#define OUT_CH    2

#define SCAN_CHUNK 1024
#define NB ((N_NODES + SCAN_CHUNK - 1) / SCAN_CHUNK)   // 98

__device__ __forceinline__ u32 bf2_bits(__nv_bfloat162 v) {
    u32 u;
    memcpy(&u, &v, 4);
    return u;
}

// ---------------- scratch ----------------
__device__ u64   g_degcnt[N_NODES]; // {cnt<<40 | fx16 sum|w|}
__device__ float g_deg[N_NODES];    // dinv
__device__ int   g_cnt[N_NODES];
__device__ int   g_cursor[N_NODES];
__device__ int   g_starts[N_NODES + 1];
__device__ int   g_bsum[128];
__device__ int2  g_edges[N_EDGES];  // {src, |w| bits}
__device__ float g_bufA[(size_t)N_NODES * HID];  // raw x@W1, later t
__device__ uint4 g_hbf [(size_t)N_NODES * 8];    // bf16 h' rows (128B/row)
__device__ uint4 g_hbf2[(size_t)N_NODES * 8];    // bf16 dinv*relu1 rows
__device__ float g_pooled[N_GRAPHS * HID];
__device__ int   g_cntg[N_GRAPHS];

// ---------------- init ----------------
__global__ void k_zero() {
    int i = blockIdx.x * blockDim.x + threadIdx.x;
    if (i < N_NODES) g_degcnt[i] = 0ULL;
    if (i < N_GRAPHS * HID) g_pooled[i] = 0.f;
    if (i < N_GRAPHS) g_cntg[i] = 0;
}

__global__ void k_cntg(const int* __restrict__ batch) {
    int i = blockIdx.x * blockDim.x + threadIdx.x;
    if (i < N_NODES) atomicAdd(&g_cntg[batch[i]], 1);
}

// ---------------- packed degree histogram (1 atomic / edge) ----------------
__global__ void k_hist(const int4* __restrict__ col4, const float4* __restrict__ wa4) {
    int i = blockIdx.x * blockDim.x + threadIdx.x;
    if (i >= N_EDGES / 4) return;
    int4   c = col4[i];
    float4 w = wa4[i];
    const u64 ONE = 1ULL << 40;
    atomicAdd(&g_degcnt[c.x], ONE + (u64)(fabsf(w.x) * 65536.0f + 0.5f));
    atomicAdd(&g_degcnt[c.y], ONE + (u64)(fabsf(w.y) * 65536.0f + 0.5f));
    atomicAdd(&g_degcnt[c.z], ONE + (u64)(fabsf(w.z) * 65536.0f + 0.5f));
    atomicAdd(&g_degcnt[c.w], ONE + (u64)(fabsf(w.w) * 65536.0f + 0.5f));
}

__global__ void k_dinv() {
    int i = blockIdx.x * blockDim.x + threadIdx.x;
    if (i >= N_NODES) return;
    u64 v = g_degcnt[i];
    g_cnt[i] = (int)(v >> 40);
    float deg = (float)((double)(v & ((1ULL << 40) - 1)) * (1.0 / 65536.0));
    g_deg[i] = rsqrtf(deg + 1.0f);
}

// ---------------- exclusive scan ----------------
__global__ void k_scan1() {
    __shared__ int sh[SCAN_CHUNK];
    int idx = blockIdx.x * SCAN_CHUNK + threadIdx.x;
    sh[threadIdx.x] = (idx < N_NODES) ? g_cnt[idx] : 0;
    __syncthreads();
    for (int off = SCAN_CHUNK / 2; off > 0; off >>= 1) {
        if (threadIdx.x < off) sh[threadIdx.x] += sh[threadIdx.x + off];
        __syncthreads();
    }
    if (threadIdx.x == 0) g_bsum[blockIdx.x] = sh[0];
}

__global__ void k_scan2() {
    __shared__ int sh[128];
    int t = threadIdx.x;
    sh[t] = (t < NB) ? g_bsum[t] : 0;
    __syncthreads();
    if (t == 0) {
        int acc = 0;
        for (int b = 0; b < NB; b++) { int v = sh[b]; g_bsum[b] = acc; acc += v; }
        g_starts[N_NODES] = N_EDGES;
    }
}

__global__ void k_scan3() {
    __shared__ int sh[SCAN_CHUNK];
    int idx = blockIdx.x * SCAN_CHUNK + threadIdx.x;
    int v = (idx < N_NODES) ? g_cnt[idx] : 0;
    sh[threadIdx.x] = v;
    __syncthreads();
    for (int off = 1; off < SCAN_CHUNK; off <<= 1) {
        int t = (threadIdx.x >= off) ? sh[threadIdx.x - off] : 0;
        __syncthreads();
        sh[threadIdx.x] += t;
        __syncthreads();
    }
    if (idx < N_NODES) {
        int st = g_bsum[blockIdx.x] + sh[threadIdx.x] - v;
        g_starts[idx] = st;
        g_cursor[idx] = st;
    }
}

// ---------------- CSR fill ----------------
__global__ void k_fill(const int4* __restrict__ row4, const int4* __restrict__ col4,
                       const float4* __restrict__ wa4) {
    int i = blockIdx.x * blockDim.x + threadIdx.x;
    if (i >= N_EDGES / 4) return;
    int4   r = row4[i];
    int4   c = col4[i];
    float4 w = wa4[i];
    int p;
    p = atomicAdd(&g_cursor[c.x], 1); g_edges[p] = make_int2(r.x, __float_as_int(fabsf(w.x)));
    p = atomicAdd(&g_cursor[c.y], 1); g_edges[p] = make_int2(r.y, __float_as_int(fabsf(w.y)));
    p = atomicAdd(&g_cursor[c.z], 1); g_edges[p] = make_int2(r.z, __float_as_int(fabsf(w.z)));
    p = atomicAdd(&g_cursor[c.w], 1); g_edges[p] = make_int2(r.w, __float_as_int(fabsf(w.w)));
}

// ============ warp-MMA GEMM1 (mma.sync m16n8k16 bf16): bufA = x @ W1 =======
// 256 threads = 8 warps; block output tile 128 x 64; warp = 16-row strip.
// K = 200 padded to 208 (13 steps of 16). A, W1^T staged in padded SMEM.
#define SA 216                      // bf16 row stride (pad: conflict-free frags)
#define MM_B_OFF (128 * SA * 2)     // 55296
#define MM_SMEM  (MM_B_OFF + 64 * SA * 2)  // 82944

__global__ void __launch_bounds__(256) k_gemm1_mma(const float* __restrict__ x,
                                                   const float* __restrict__ W1) {
    extern __shared__ __align__(16) char smem[];
    __nv_bfloat16* As = (__nv_bfloat16*)smem;               // [128][SA]
    __nv_bfloat16* Bs = (__nv_bfloat16*)(smem + MM_B_OFF);  // [64][SA] = W1^T
    int tid = threadIdx.x;
    int m0  = blockIdx.x * 128;

    // zero K-pad cols 200..207
    for (int i = tid; i < 128 * 4; i += 256) {
        int r = i >> 2, c = 200 + ((i & 3) << 1);
        *(u32*)(As + r * SA + c) = 0;
    }
    for (int i = tid; i < 64 * 4; i += 256) {
        int r = i >> 2, c = 200 + ((i & 3) << 1);
        *(u32*)(Bs + r * SA + c) = 0;
    }
    // fill A: coalesced float4 reads of x, convert to bf16
    for (int f = tid; f < 128 * 50; f += 256) {
        int r = f / 50, c4 = f % 50;
        int mg = m0 + r;
        float4 v = make_float4(0.f, 0.f, 0.f, 0.f);
        if (mg < N_NODES) v = *(const float4*)(x + (size_t)mg * IN_CH + c4 * 4);
        u32 p0 = bf2_bits(__float22bfloat162_rn(make_float2(v.x, v.y)));
        u32 p1 = bf2_bits(__float22bfloat162_rn(make_float2(v.z, v.w)));
        *(uint2*)(As + r * SA + c4 * 4) = make_uint2(p0, p1);
    }
    // fill B = W1^T (coalesced read of W1[k][n], scatter 16-bit store)
    for (int idx = tid; idx < IN_CH * HID; idx += 256) {
        int k = idx / HID, n = idx % HID;
        Bs[n * SA + k] = __float2bfloat16(W1[idx]);
    }
    __syncthreads();

    int warp = tid >> 5, lane = tid & 31;
    int grp = lane >> 2, t4 = lane & 3;
    const __nv_bfloat16* Ar0 = As + (warp * 16 + grp) * SA;
    const __nv_bfloat16* Ar1 = Ar0 + 8 * SA;

    float c[8][4];
#pragma unroll
    for (int nt = 0; nt < 8; nt++)
#pragma unroll
        for (int j = 0; j < 4; j++) c[nt][j] = 0.f;

#pragma unroll
    for (int s = 0; s < 13; s++) {
        int k0 = s * 16;
        u32 a0 = *(const u32*)(Ar0 + k0 + 2 * t4);
        u32 a1 = *(const u32*)(Ar1 + k0 + 2 * t4);
        u32 a2 = *(const u32*)(Ar0 + k0 + 2 * t4 + 8);
        u32 a3 = *(const u32*)(Ar1 + k0 + 2 * t4 + 8);
#pragma unroll
        for (int nt = 0; nt < 8; nt++) {
            const __nv_bfloat16* Bp = Bs + (nt * 8 + grp) * SA + k0 + 2 * t4;
            u32 b0 = *(const u32*)(Bp);
            u32 b1 = *(const u32*)(Bp + 8);
            asm volatile(
                "mma.sync.aligned.m16n8k16.row.col.f32.bf16.bf16.f32 "
                "{%0,%1,%2,%3}, {%4,%5,%6,%7}, {%8,%9}, {%0,%1,%2,%3};"
                : "+f"(c[nt][0]), "+f"(c[nt][1]), "+f"(c[nt][2]), "+f"(c[nt][3])
                : "r"(a0), "r"(a1), "r"(a2), "r"(a3), "r"(b0), "r"(b1));
        }
    }

    int mA = m0 + warp * 16 + grp;
    int mB = mA + 8;
#pragma unroll
    for (int nt = 0; nt < 8; nt++) {
        int col = nt * 8 + 2 * t4;
        if (mA < N_NODES)
            *(float2*)(g_bufA + (size_t)mA * 64 + col) = make_float2(c[nt][0], c[nt][1]);
        if (mB < N_NODES)
            *(float2*)(g_bufA + (size_t)mB * 64 + col) = make_float2(c[nt][2], c[nt][3]);
    }
}

// ---------------- fp32 SIMT GEMM (layer 2 + fused pooling) -----------------
template <int K>
__device__ __forceinline__ void gemm_pool_impl(const float* __restrict__ A,
                                               const float* __restrict__ W,
                                               const float* __restrict__ bias,
                                               const int* __restrict__ batch) {
    __shared__ __align__(16) float xs[8][128];
    __shared__ __align__(16) float ws[8][64];
    const int M = N_NODES;
    int tid = threadIdx.x;
    int m0  = blockIdx.x * 128;
    int r0  = (tid >> 4) * 8;
    int c0  = (tid & 15) * 4;

    float4 acc[8];
#pragma unroll
    for (int i = 0; i < 8; i++) acc[i] = make_float4(0.f, 0.f, 0.f, 0.f);

    int ml = tid & 127;
    int kq = (tid >> 7) * 4;
    int mg = m0 + ml;
    const float* Arow = A + (size_t)mg * K;

    for (int k0 = 0; k0 < K; k0 += 8) {
        float4 xv = make_float4(0.f, 0.f, 0.f, 0.f);
        if (mg < M) xv = *(const float4*)(Arow + k0 + kq);
        if (tid < 128) {
            int kk = tid >> 4;
            int c  = (tid & 15) * 4;
            *(float4*)&ws[kk][c] = *(const float4*)(W + (k0 + kk) * 64 + c);
        }
        xs[kq + 0][ml] = xv.x;
        xs[kq + 1][ml] = xv.y;
        xs[kq + 2][ml] = xv.z;
        xs[kq + 3][ml] = xv.w;
        __syncthreads();
#pragma unroll
        for (int kk = 0; kk < 8; kk++) {
            float4 w4 = *(float4*)&ws[kk][c0];
            float4 a0 = *(float4*)&xs[kk][r0];
            float4 a1 = *(float4*)&xs[kk][r0 + 4];
            float a[8] = {a0.x, a0.y, a0.z, a0.w, a1.x, a1.y, a1.z, a1.w};
#pragma unroll
            for (int i = 0; i < 8; i++) {
                acc[i].x = fmaf(a[i], w4.x, acc[i].x);
                acc[i].y = fmaf(a[i], w4.y, acc[i].y);
                acc[i].z = fmaf(a[i], w4.z, acc[i].z);
                acc[i].w = fmaf(a[i], w4.w, acc[i].w);
            }
        }
        __syncthreads();
    }
    float4 bv = *(const float4*)(bias + c0);
#pragma unroll
    for (int i = 0; i < 8; i++) {
        int m = m0 + r0 + i;
        if (m < M) {
            float4 v = acc[i];
            v.x = fmaxf(v.x + bv.x, 0.f);
            v.y = fmaxf(v.y + bv.y, 0.f);
            v.z = fmaxf(v.z + bv.z, 0.f);
            v.w = fmaxf(v.w + bv.w, 0.f);
            int g = batch[m];
            float* dst = g_pooled + g * 64 + c0;
#if __CUDA_ARCH__ >= 900
            atomicAdd((float4*)dst, v);
#else
            atomicAdd(dst + 0, v.x);
            atomicAdd(dst + 1, v.y);
            atomicAdd(dst + 2, v.z);
            atomicAdd(dst + 3, v.w);
#endif
        }
    }
}

__global__ void __launch_bounds__(256) k_gemm2pool(const float* __restrict__ W2,
                                                   const float* __restrict__ b2,
                                                   const int* __restrict__ batch) {
    gemm_pool_impl<HID>(g_bufA, W2, b2, batch);
}

// ---------------- convert bufA -> bf16 with dinv scale ----------------
__global__ void k_conv() {
    int i = blockIdx.x * blockDim.x + threadIdx.x;   // one uint4 (8 feats) / thread
    if (i >= N_NODES * 8) return;
    int n = i >> 3;
    float d = g_deg[n];
    const float* src = g_bufA + (size_t)i * 8;
    float4 v0 = *(const float4*)(src);
    float4 v1 = *(const float4*)(src + 4);
    uint4 o;
    o.x = bf2_bits(__float22bfloat162_rn(make_float2(v0.x * d, v0.y * d)));
    o.y = bf2_bits(__float22bfloat162_rn(make_float2(v0.z * d, v0.w * d)));
    o.z = bf2_bits(__float22bfloat162_rn(make_float2(v1.x * d, v1.y * d)));
    o.w = bf2_bits(__float22bfloat162_rn(make_float2(v1.z * d, v1.w * d)));
    g_hbf[i] = o;
}

// ---- 4-edges-per-warp gather: 8 lanes/edge, 0.5 LDG per edge --------------
__device__ __forceinline__ void gather_core(const uint4* __restrict__ h,
                                            int s, int e, int eg, int fl,
                                            float acc[8]) {
#pragma unroll 2
    for (int i = s; i < e; i += 4) {
        int idx = i + eg;
        int cl  = idx < e ? idx : (e - 1);
        int2 ed = g_edges[cl];
        float w = idx < e ? __int_as_float(ed.y) : 0.f;
        uint4 hv = h[(size_t)ed.x * 8 + fl];
        float2 p0 = __bfloat1622float2(*(__nv_bfloat162*)&hv.x);
        float2 p1 = __bfloat1622float2(*(__nv_bfloat162*)&hv.y);
        float2 p2 = __bfloat1622float2(*(__nv_bfloat162*)&hv.z);
        float2 p3 = __bfloat1622float2(*(__nv_bfloat162*)&hv.w);
        acc[0] = fmaf(w, p0.x, acc[0]);
        acc[1] = fmaf(w, p0.y, acc[1]);
        acc[2] = fmaf(w, p1.x, acc[2]);
        acc[3] = fmaf(w, p1.y, acc[3]);
        acc[4] = fmaf(w, p2.x, acc[4]);
        acc[5] = fmaf(w, p2.y, acc[5]);
        acc[6] = fmaf(w, p3.x, acc[6]);
        acc[7] = fmaf(w, p3.y, acc[7]);
    }
#pragma unroll
    for (int k = 0; k < 8; k++) {
        acc[k] += __shfl_xor_sync(0xffffffffu, acc[k], 8);
        acc[k] += __shfl_xor_sync(0xffffffffu, acc[k], 16);
    }
}

// layer 1: g_hbf2[n] = bf16( dinv * relu( dinv*(sum + hn) + b1 ) )
__global__ void __launch_bounds__(256) k_gather1(const float* __restrict__ bias) {
    int wid  = (blockIdx.x * blockDim.x + threadIdx.x) >> 5;
    int lane = threadIdx.x & 31;
    if (wid >= N_NODES) return;
    int s = g_starts[wid];
    int e = g_starts[wid + 1];
    int eg = lane >> 3;
    int fl = lane & 7;
    float acc[8] = {0.f, 0.f, 0.f, 0.f, 0.f, 0.f, 0.f, 0.f};
    gather_core(g_hbf, s, e, eg, fl, acc);
    if (eg == 0) {
        uint4 hn = g_hbf[(size_t)wid * 8 + fl];
        float2 q0 = __bfloat1622float2(*(__nv_bfloat162*)&hn.x);
        float2 q1 = __bfloat1622float2(*(__nv_bfloat162*)&hn.y);
        float2 q2 = __bfloat1622float2(*(__nv_bfloat162*)&hn.z);
        float2 q3 = __bfloat1622float2(*(__nv_bfloat162*)&hn.w);
        float d = g_deg[wid];
        float4 bA = *(const float4*)(bias + fl * 8);
        float4 bB = *(const float4*)(bias + fl * 8 + 4);
        float o0 = fmaxf(fmaf(d, acc[0] + q0.x, bA.x), 0.f) * d;
        float o1 = fmaxf(fmaf(d, acc[1] + q0.y, bA.y), 0.f) * d;
        float o2 = fmaxf(fmaf(d, acc[2] + q1.x, bA.z), 0.f) * d;
        float o3 = fmaxf(fmaf(d, acc[3] + q1.y, bA.w), 0.f) * d;
        float o4 = fmaxf(fmaf(d, acc[4] + q2.x, bB.x), 0.f) * d;
        float o5 = fmaxf(fmaf(d, acc[5] + q2.y, bB.y), 0.f) * d;
        float o6 = fmaxf(fmaf(d, acc[6] + q3.x, bB.z), 0.f) * d;
        float o7 = fmaxf(fmaf(d, acc[7] + q3.y, bB.w), 0.f) * d;
        uint4 o;
        o.x = bf2_bits(__float22bfloat162_rn(make_float2(o0, o1)));
        o.y = bf2_bits(__float22bfloat162_rn(make_float2(o2, o3)));
        o.z = bf2_bits(__float22bfloat162_rn(make_float2(o4, o5)));
        o.w = bf2_bits(__float22bfloat162_rn(make_float2(o6, o7)));
        g_hbf2[(size_t)wid * 8 + fl] = o;
    }
}

// layer 2: g_bufA[n,:] = dinv*(sum + hn)   (fp32)
__global__ void __launch_bounds__(256) k_gather2() {
    int wid  = (blockIdx.x * blockDim.x + threadIdx.x) >> 5;
    int lane = threadIdx.x & 31;
    if (wid >= N_NODES) return;
    int s = g_starts[wid];
    int e = g_starts[wid + 1];
    int eg = lane >> 3;
    int fl = lane & 7;
    float acc[8] = {0.f, 0.f, 0.f, 0.f, 0.f, 0.f, 0.f, 0.f};
    gather_core(g_hbf2, s, e, eg, fl, acc);
    if (eg == 0) {
        uint4 hn = g_hbf2[(size_t)wid * 8 + fl];
        float2 q0 = __bfloat1622float2(*(__nv_bfloat162*)&hn.x);
        float2 q1 = __bfloat1622float2(*(__nv_bfloat162*)&hn.y);
        float2 q2 = __bfloat1622float2(*(__nv_bfloat162*)&hn.z);
        float2 q3 = __bfloat1622float2(*(__nv_bfloat162*)&hn.w);
        float d = g_deg[wid];
        float* dst = g_bufA + (size_t)wid * 64 + fl * 8;
        float4 oA, oB;
        oA.x = d * (acc[0] + q0.x);
        oA.y = d * (acc[1] + q0.y);
        oA.z = d * (acc[2] + q1.x);
        oA.w = d * (acc[3] + q1.y);
        oB.x = d * (acc[4] + q2.x);
        oB.y = d * (acc[5] + q2.y);
        oB.z = d * (acc[6] + q3.x);
        oB.w = d * (acc[7] + q3.y);
        *(float4*)(dst)     = oA;
        *(float4*)(dst + 4) = oB;
    }
}

// ---------------- final MLP ----------------
__global__ void __launch_bounds__(256) k_mlp(const float* __restrict__ L1,
                                             const float* __restrict__ c1,
                                             const float* __restrict__ L2,
                                             const float* __restrict__ c2,
                                             float* __restrict__ out) {
    int g = blockIdx.x;
    __shared__ float pm[HID];
    __shared__ float fea[IN_CH];
    __shared__ float red[256];
    int tid = threadIdx.x;
    if (tid < HID) {
        float cv = (float)g_cntg[g];
        pm[tid] = g_pooled[g * HID + tid] / fmaxf(cv, 1.0f);
    }
    __syncthreads();
    if (tid < IN_CH) {
        float s = c1[tid];
#pragma unroll
        for (int k = 0; k < HID; k++) s = fmaf(pm[k], L1[k * IN_CH + tid], s);
        fea[tid] = fmaxf(s, 0.f);
    }
    __syncthreads();
    float p0 = 0.f, p1 = 0.f;
    if (tid < IN_CH) {
        float fv = fea[tid];
        p0 = fv * L2[tid * OUT_CH];
        p1 = fv * L2[tid * OUT_CH + 1];
    }
    red[tid] = p0; __syncthreads();
    for (int off = 128; off > 0; off >>= 1) {
        if (tid < off) red[tid] += red[tid + off];
        __syncthreads();
    }
    float s0 = red[0];
    __syncthreads();
    red[tid] = p1; __syncthreads();
    for (int off = 128; off > 0; off >>= 1) {
        if (tid < off) red[tid] += red[tid + off];
        __syncthreads();
    }
    if (tid == 0) {
        out[g * OUT_CH]     = s0     + c2[0];
        out[g * OUT_CH + 1] = red[0] + c2[1];
    }
}

// ---------------- launch ----------------
extern "C" void kernel_launch(void* const* d_in, const int* in_sizes, int n_in,
                              void* d_out, int out_size) {
    const float* x         = (const float*)d_in[0];
    const int*   edge_idx  = (const int*)d_in[1];
    const float* edge_attr = (const float*)d_in[2];
    const int*   batch     = (const int*)d_in[3];
    const float* W1        = (const float*)d_in[4];
    const float* b1        = (const float*)d_in[5];
    const float* W2        = (const float*)d_in[6];
    const float* b2        = (const float*)d_in[7];
    const float* L1        = (const float*)d_in[8];
    const float* c1        = (const float*)d_in[9];
    const float* L2        = (const float*)d_in[10];
    const float* c2        = (const float*)d_in[11];
    float* out = (float*)d_out;

    const int* row = edge_idx;
    const int* col = edge_idx + N_EDGES;

    static cudaStream_t s2 = nullptr;
    static cudaEvent_t  evF = nullptr, evD = nullptr, evJ = nullptr;
    if (s2 == nullptr) {
        cudaStreamCreateWithFlags(&s2, cudaStreamNonBlocking);
        cudaEventCreateWithFlags(&evF, cudaEventDisableTiming);
        cudaEventCreateWithFlags(&evD, cudaEventDisableTiming);
        cudaEventCreateWithFlags(&evJ, cudaEventDisableTiming);
        cudaFuncSetAttribute(k_gemm1_mma, cudaFuncAttributeMaxDynamicSharedMemorySize,
                             MM_SMEM);
    }

    const int TB = 256;
    int nodeBlocks   = (N_NODES + TB - 1) / TB;
    int edge4Blocks  = (N_EDGES / 4 + TB - 1) / TB;
    int gemmBlocks   = (N_NODES + 127) / 128;
    int gatherBlocks = (N_NODES * 32 + TB - 1) / TB;
    int convBlocks   = (N_NODES * 8 + TB - 1) / TB;

    // fork: MMA GEMM1 has no dependencies
    cudaEventRecord(evF, 0);
    cudaStreamWaitEvent(s2, evF, 0);
    k_gemm1_mma<<<gemmBlocks, 256, MM_SMEM, s2>>>(x, W1);  // bufA = x @ W1 (raw)

    k_zero<<<nodeBlocks, TB>>>();
    k_cntg<<<nodeBlocks, TB>>>(batch);
    k_hist<<<edge4Blocks, TB>>>((const int4*)col, (const float4*)edge_attr);
    k_dinv<<<nodeBlocks, TB>>>();
    cudaEventRecord(evD, 0);                          // dinv ready

    cudaStreamWaitEvent(s2, evD, 0);
    k_conv<<<convBlocks, TB, 0, s2>>>();              // g_hbf = bf16(dinv*bufA)
    cudaEventRecord(evJ, s2);

    k_scan1<<<NB, SCAN_CHUNK>>>();
    k_scan2<<<1, 128>>>();
    k_scan3<<<NB, SCAN_CHUNK>>>();
    k_fill<<<edge4Blocks, TB>>>((const int4*)row, (const int4*)col,
                                (const float4*)edge_attr);

    cudaStreamWaitEvent(0, evJ, 0);                   // join

    k_gather1<<<gatherBlocks, TB>>>(b1);              // g_hbf2 = dinv*relu1 (bf16)
    k_gather2<<<gatherBlocks, TB>>>();                // bufA = t (fp32)
    k_gemm2pool<<<gemmBlocks, 256>>>(W2, b2, batch);  // pooled += relu(t@W2+b2)
    k_mlp<<<N_GRAPHS, 256>>>(L1, c1, L2, c2, out);
}